// round 1
// baseline (speedup 1.0000x reference)
#include <cuda_runtime.h>
#include <math.h>

// Problem constants (fixed by the dataset)
#define NN 25000
#define EE 400000
#define HH 4
#define CC 128
#define DD 128
#define HC 512           // H*C
#define SCALE 0.08838834764831845f   // 1/sqrt(128)

// ------------------------- device scratch (no runtime allocs) ---------------
static __device__ int   g_row[NN + 1];
static __device__ int   g_cnt[NN + 1];
static __device__ int   g_cursor[NN + 1];
static __device__ int   g_srcs[EE];
static __device__ float g_q[NN * HC];
static __device__ float g_k[NN * HC];
static __device__ float g_v[NN * HC];
static __device__ float g_s[NN * DD];
static __device__ float g_hA[NN * DD];
static __device__ float g_hB[NN * DD];
static __device__ float g_g[DD];

// ------------------------- CSR build ----------------------------------------
__global__ void hist_kernel(const int* __restrict__ dst, int* __restrict__ cnt) {
    int e = blockIdx.x * blockDim.x + threadIdx.x;
    if (e < EE) atomicAdd(&cnt[dst[e]], 1);
}

// single-block exclusive scan over NN entries -> row & cursor
__global__ void scan_kernel(const int* __restrict__ cnt,
                            int* __restrict__ row, int* __restrict__ cursor) {
    __shared__ int buf[1024];
    __shared__ int carry;
    int tid = threadIdx.x;
    if (tid == 0) carry = 0;
    __syncthreads();
    for (int base = 0; base < NN; base += 1024) {
        int i = base + tid;
        int v = (i < NN) ? cnt[i] : 0;
        buf[tid] = v;
        __syncthreads();
        #pragma unroll
        for (int off = 1; off < 1024; off <<= 1) {
            int t = (tid >= off) ? buf[tid - off] : 0;
            __syncthreads();
            buf[tid] += t;
            __syncthreads();
        }
        int incl = buf[tid];
        int excl = incl - v + carry;
        if (i < NN) { row[i] = excl; cursor[i] = excl; }
        __syncthreads();
        if (tid == 1023) carry += buf[1023];
        __syncthreads();
    }
    if (tid == 0) row[NN] = carry;
}

__global__ void fill_kernel(const int* __restrict__ src, const int* __restrict__ dst,
                            int* __restrict__ cursor, int* __restrict__ srcs) {
    int e = blockIdx.x * blockDim.x + threadIdx.x;
    if (e < EE) {
        int p = atomicAdd(&cursor[dst[e]], 1);
        srcs[p] = src[e];
    }
}

// ------------------------- GEMM: Y = X*W + b --------------------------------
// X: [rows x K] row-major, W: [K x OC] row-major, Y: [rows x OC]
// 64x64 tile, BK=16, 256 threads, 4x4 per thread.
__global__ void gemm_bias_kernel(const float* __restrict__ X, const float* __restrict__ W,
                                 const float* __restrict__ b, float* __restrict__ Y,
                                 int rows, int K, int OC) {
    __shared__ float sX[16][64];
    __shared__ float sW[16][64];
    int tid = threadIdx.x;
    int tm = (tid / 16) * 4;
    int tn = (tid % 16) * 4;
    int blockRow = blockIdx.y * 64;
    int blockCol = blockIdx.x * 64;
    float acc[4][4];
    #pragma unroll
    for (int i = 0; i < 4; i++)
        #pragma unroll
        for (int j = 0; j < 4; j++) acc[i][j] = 0.f;

    for (int k0 = 0; k0 < K; k0 += 16) {
        // load X tile (64 x 16), store transposed sX[k][m]
        #pragma unroll
        for (int i = tid; i < 64 * 16; i += 256) {
            int m = i >> 4, k = i & 15;
            int gr = blockRow + m;
            sX[k][m] = (gr < rows) ? X[gr * K + k0 + k] : 0.f;
        }
        // load W tile (16 x 64)
        #pragma unroll
        for (int i = tid; i < 16 * 64; i += 256) {
            int k = i >> 6, n = i & 63;
            sW[k][n] = W[(k0 + k) * OC + blockCol + n];
        }
        __syncthreads();
        #pragma unroll
        for (int k = 0; k < 16; ++k) {
            float a[4], bb[4];
            #pragma unroll
            for (int i = 0; i < 4; i++) a[i] = sX[k][tm + i];
            #pragma unroll
            for (int j = 0; j < 4; j++) bb[j] = sW[k][tn + j];
            #pragma unroll
            for (int i = 0; i < 4; i++)
                #pragma unroll
                for (int j = 0; j < 4; j++) acc[i][j] += a[i] * bb[j];
        }
        __syncthreads();
    }
    #pragma unroll
    for (int i = 0; i < 4; i++) {
        int gr = blockRow + tm + i;
        if (gr < rows) {
            #pragma unroll
            for (int j = 0; j < 4; j++)
                Y[gr * OC + blockCol + tn + j] = acc[i][j] + b[blockCol + tn + j];
        }
    }
}

// ------------------------- fused attention per node -------------------------
// block = 128 threads (4 warps, warp h = head h), one block per dst node.
// online softmax over incoming edges, then head-mean + skip + relu.
__global__ void attn_kernel(const float* __restrict__ q, const float* __restrict__ k,
                            const float* __restrict__ v, const float* __restrict__ s,
                            const int* __restrict__ row, const int* __restrict__ srcs,
                            float* __restrict__ out) {
    int n = blockIdx.x;
    int tid = threadIdx.x;
    int h = tid >> 5;
    int lane = tid & 31;
    __shared__ float sh[HH][CC];

    const float4 qv = reinterpret_cast<const float4*>(q + (size_t)n * HC + h * CC)[lane];
    int beg = row[n], end = row[n + 1];

    float m = -INFINITY, l = 0.f;
    float4 acc = make_float4(0.f, 0.f, 0.f, 0.f);

    for (int j = beg; j < end; ++j) {
        int sidx = srcs[j];
        const float4 kv = reinterpret_cast<const float4*>(k + (size_t)sidx * HC + h * CC)[lane];
        float part = qv.x * kv.x + qv.y * kv.y + qv.z * kv.z + qv.w * kv.w;
        #pragma unroll
        for (int off = 16; off > 0; off >>= 1)
            part += __shfl_xor_sync(0xffffffffu, part, off);
        float alpha = part * SCALE;
        float m2 = fmaxf(m, alpha);
        float cf = expf(m - m2);       // 0 on first edge (m = -inf)
        float p  = expf(alpha - m2);
        const float4 vv = reinterpret_cast<const float4*>(v + (size_t)sidx * HC + h * CC)[lane];
        acc.x = acc.x * cf + p * vv.x;
        acc.y = acc.y * cf + p * vv.y;
        acc.z = acc.z * cf + p * vv.z;
        acc.w = acc.w * cf + p * vv.w;
        l = l * cf + p;
        m = m2;
    }
    float invl = 1.f / (l + 1e-16f);
    sh[h][lane * 4 + 0] = acc.x * invl;
    sh[h][lane * 4 + 1] = acc.y * invl;
    sh[h][lane * 4 + 2] = acc.z * invl;
    sh[h][lane * 4 + 3] = acc.w * invl;
    __syncthreads();

    // tid indexes channel 0..127
    float val = (sh[0][tid] + sh[1][tid] + sh[2][tid] + sh[3][tid]) * 0.25f
              + s[(size_t)n * DD + tid];
    out[(size_t)n * DD + tid] = fmaxf(val, 0.f);
}

// ------------------------- tail: mean over nodes, fc, sigmoid ---------------
__global__ void reduce_cols_kernel(const float* __restrict__ hbuf, float* __restrict__ g) {
    int c = threadIdx.x;          // 128 channels
    float a = 0.f;
    for (int r = blockIdx.x; r < NN; r += gridDim.x)
        a += hbuf[(size_t)r * DD + c];
    atomicAdd(&g[c], a);
}

__global__ void fc_kernel(const float* __restrict__ g, const float* __restrict__ Wfc,
                          const float* __restrict__ bfc, float* __restrict__ out) {
    int tid = threadIdx.x;        // 128
    float x = g[tid] * (1.0f / (float)NN) * Wfc[tid];
    #pragma unroll
    for (int off = 16; off > 0; off >>= 1)
        x += __shfl_xor_sync(0xffffffffu, x, off);
    __shared__ float ws[4];
    if ((tid & 31) == 0) ws[tid >> 5] = x;
    __syncthreads();
    if (tid == 0) {
        float sum = ws[0] + ws[1] + ws[2] + ws[3] + bfc[0];
        out[0] = 1.f / (1.f + expf(-sum));
    }
}

// ------------------------- launch -------------------------------------------
extern "C" void kernel_launch(void* const* d_in, const int* in_sizes, int n_in,
                              void* d_out, int out_size) {
    (void)in_sizes; (void)n_in; (void)out_size;

    const float* x        = (const float*)d_in[0];
    const int*   eidx     = (const int*)d_in[1];
    const int*   src      = eidx;
    const int*   dst      = eidx + EE;
    const float* Wfc      = (const float*)d_in[26];
    const float* bfc      = (const float*)d_in[27];
    float* out = (float*)d_out;

    // scratch pointers
    int *row, *cnt, *cursor, *srcs;
    float *q, *k, *v, *s, *hA, *hB, *g;
    cudaGetSymbolAddress((void**)&row,    g_row);
    cudaGetSymbolAddress((void**)&cnt,    g_cnt);
    cudaGetSymbolAddress((void**)&cursor, g_cursor);
    cudaGetSymbolAddress((void**)&srcs,   g_srcs);
    cudaGetSymbolAddress((void**)&q,      g_q);
    cudaGetSymbolAddress((void**)&k,      g_k);
    cudaGetSymbolAddress((void**)&v,      g_v);
    cudaGetSymbolAddress((void**)&s,      g_s);
    cudaGetSymbolAddress((void**)&hA,     g_hA);
    cudaGetSymbolAddress((void**)&hB,     g_hB);
    cudaGetSymbolAddress((void**)&g,      g_g);

    // ---- CSR build (once per launch; edge_index identical for all layers) ----
    cudaMemsetAsync(cnt, 0, (NN + 1) * sizeof(int), 0);
    hist_kernel<<<(EE + 255) / 256, 256>>>(dst, cnt);
    scan_kernel<<<1, 1024>>>(cnt, row, cursor);
    fill_kernel<<<(EE + 255) / 256, 256>>>(src, dst, cursor, srcs);

    // ---- 3 transformer-conv layers ----
    const float* X = x;
    int fin = 64;
    float* hout = hA;
    for (int l = 0; l < 3; ++l) {
        const float* Wq = (const float*)d_in[2 + 8 * l + 0];
        const float* bq = (const float*)d_in[2 + 8 * l + 1];
        const float* Wk = (const float*)d_in[2 + 8 * l + 2];
        const float* bk = (const float*)d_in[2 + 8 * l + 3];
        const float* Wv = (const float*)d_in[2 + 8 * l + 4];
        const float* bv = (const float*)d_in[2 + 8 * l + 5];
        const float* Ws = (const float*)d_in[2 + 8 * l + 6];
        const float* bs = (const float*)d_in[2 + 8 * l + 7];

        dim3 gridQKV(HC / 64, (NN + 63) / 64);
        dim3 gridS(DD / 64, (NN + 63) / 64);
        gemm_bias_kernel<<<gridQKV, 256>>>(X, Wq, bq, q, NN, fin, HC);
        gemm_bias_kernel<<<gridQKV, 256>>>(X, Wk, bk, k, NN, fin, HC);
        gemm_bias_kernel<<<gridQKV, 256>>>(X, Wv, bv, v, NN, fin, HC);
        gemm_bias_kernel<<<gridS,   256>>>(X, Ws, bs, s, NN, fin, DD);

        attn_kernel<<<NN, 128>>>(q, k, v, s, row, srcs, hout);

        X = hout;
        hout = (hout == hA) ? hB : hA;
        fin = DD;
    }

    // ---- global mean + fc + sigmoid ----
    cudaMemsetAsync(g, 0, DD * sizeof(float), 0);
    reduce_cols_kernel<<<256, 128>>>(X, g);
    fc_kernel<<<1, 128>>>(g, Wfc, bfc, out);
}

// round 2
// speedup vs baseline: 1.6506x; 1.6506x over previous
#include <cuda_runtime.h>
#include <math.h>

// Problem constants (fixed by the dataset)
#define NN 25000
#define EE 400000
#define HH 4
#define CC 128
#define DD 128
#define HC 512           // H*C
#define SCALE 0.08838834764831845f   // 1/sqrt(128)

// ------------------------- device scratch (no runtime allocs) ---------------
static __device__ int   g_row[NN + 1];
static __device__ int   g_cnt[NN + 1];
static __device__ int   g_cursor[NN + 1];
static __device__ int   g_srcs[EE];
static __device__ float g_q[NN * HC];
static __device__ float g_k[NN * HC];
static __device__ float g_v[NN * HC];
static __device__ float g_s[NN * DD];
static __device__ float g_hA[NN * DD];
static __device__ float g_hB[NN * DD];
static __device__ float g_g[DD];

// ------------------------- CSR build ----------------------------------------
__global__ void hist_kernel(const int* __restrict__ dst, int* __restrict__ cnt) {
    int e = blockIdx.x * blockDim.x + threadIdx.x;
    if (e < EE) atomicAdd(&cnt[dst[e]], 1);
}

// single-block exclusive scan over NN entries -> row & cursor
__global__ void scan_kernel(const int* __restrict__ cnt,
                            int* __restrict__ row, int* __restrict__ cursor) {
    __shared__ int buf[1024];
    __shared__ int carry;
    int tid = threadIdx.x;
    if (tid == 0) carry = 0;
    __syncthreads();
    for (int base = 0; base < NN; base += 1024) {
        int i = base + tid;
        int v = (i < NN) ? cnt[i] : 0;
        buf[tid] = v;
        __syncthreads();
        #pragma unroll
        for (int off = 1; off < 1024; off <<= 1) {
            int t = (tid >= off) ? buf[tid - off] : 0;
            __syncthreads();
            buf[tid] += t;
            __syncthreads();
        }
        int incl = buf[tid];
        int excl = incl - v + carry;
        if (i < NN) { row[i] = excl; cursor[i] = excl; }
        __syncthreads();
        if (tid == 1023) carry += buf[1023];
        __syncthreads();
    }
    if (tid == 0) row[NN] = carry;
}

__global__ void fill_kernel(const int* __restrict__ src, const int* __restrict__ dst,
                            int* __restrict__ cursor, int* __restrict__ srcs) {
    int e = blockIdx.x * blockDim.x + threadIdx.x;
    if (e < EE) {
        int p = atomicAdd(&cursor[dst[e]], 1);
        srcs[p] = src[e];
    }
}

// ------------------------- fused 4-way GEMM ----------------------------------
// Y_seg = X*W_seg + b_seg for seg in {q,k,v,s}. Concatenated columns = 1664
// = 13 tiles of 128. Tiles 0-3 -> q, 4-7 -> k, 8-11 -> v, 12 -> s.
// BM=128, BN=128, BK=16, 256 threads, 8x8 per thread (4+4 split at offset 64).
__global__ __launch_bounds__(256, 2)
void gemm4_kernel(const float* __restrict__ X, int rows, int K,
                  const float* __restrict__ Wq, const float* __restrict__ bq, float* __restrict__ oq,
                  const float* __restrict__ Wk, const float* __restrict__ bk, float* __restrict__ ok,
                  const float* __restrict__ Wv, const float* __restrict__ bv, float* __restrict__ ov,
                  const float* __restrict__ Wsk, const float* __restrict__ bsk, float* __restrict__ osk)
{
    __shared__ float sX[16][128];   // transposed X tile: sX[k][m]
    __shared__ float sW[16][128];   // sW[k][n]

    int tid = threadIdx.x;
    int tile = blockIdx.x;          // 0..12
    int seg = tile >> 2;            // 0..3
    int c0 = (tile & 3) * 128;

    const float* W; const float* bias; float* Y; int oc;
    if (seg == 0)      { W = Wq;  bias = bq;  Y = oq;  oc = HC; }
    else if (seg == 1) { W = Wk;  bias = bk;  Y = ok;  oc = HC; }
    else if (seg == 2) { W = Wv;  bias = bv;  Y = ov;  oc = HC; }
    else               { W = Wsk; bias = bsk; Y = osk; oc = DD; }

    int row0 = blockIdx.y * 128;
    int rb = (tid >> 4) * 4;        // 0..60
    int cb = (tid & 15) * 4;        // 0..60

    float acc[8][8];
    #pragma unroll
    for (int i = 0; i < 8; i++)
        #pragma unroll
        for (int j = 0; j < 8; j++) acc[i][j] = 0.f;

    for (int k0 = 0; k0 < K; k0 += 16) {
        // load X tile (128 rows x 16 cols), store transposed
        #pragma unroll
        for (int t = 0; t < 2; ++t) {
            int s = tid + t * 256;      // 0..511
            int r = s >> 2;             // 0..127
            int kq = (s & 3) * 4;       // 0,4,8,12
            int gr = row0 + r;
            float4 xv = (gr < rows)
                ? *reinterpret_cast<const float4*>(X + (size_t)gr * K + k0 + kq)
                : make_float4(0.f, 0.f, 0.f, 0.f);
            sX[kq + 0][r] = xv.x;
            sX[kq + 1][r] = xv.y;
            sX[kq + 2][r] = xv.z;
            sX[kq + 3][r] = xv.w;
        }
        // load W tile (16 rows x 128 cols)
        #pragma unroll
        for (int t = 0; t < 2; ++t) {
            int s = tid + t * 256;
            int kr = s >> 5;            // 0..15
            int cq = (s & 31) * 4;      // 0..124
            *reinterpret_cast<float4*>(&sW[kr][cq]) =
                *reinterpret_cast<const float4*>(W + (size_t)(k0 + kr) * oc + c0 + cq);
        }
        __syncthreads();
        #pragma unroll
        for (int kk = 0; kk < 16; ++kk) {
            float a[8], b[8];
            *reinterpret_cast<float4*>(a)     = *reinterpret_cast<float4*>(&sX[kk][rb]);
            *reinterpret_cast<float4*>(a + 4) = *reinterpret_cast<float4*>(&sX[kk][rb + 64]);
            *reinterpret_cast<float4*>(b)     = *reinterpret_cast<float4*>(&sW[kk][cb]);
            *reinterpret_cast<float4*>(b + 4) = *reinterpret_cast<float4*>(&sW[kk][cb + 64]);
            #pragma unroll
            for (int i = 0; i < 8; ++i)
                #pragma unroll
                for (int j = 0; j < 8; ++j)
                    acc[i][j] += a[i] * b[j];
        }
        __syncthreads();
    }

    float bloc[8];
    #pragma unroll
    for (int j = 0; j < 4; ++j) {
        bloc[j]     = bias[c0 + cb + j];
        bloc[j + 4] = bias[c0 + cb + 64 + j];
    }

    #pragma unroll
    for (int i = 0; i < 8; ++i) {
        int r = row0 + rb + ((i < 4) ? i : (64 + i - 4));
        if (r < rows) {
            float4 o0 = make_float4(acc[i][0] + bloc[0], acc[i][1] + bloc[1],
                                    acc[i][2] + bloc[2], acc[i][3] + bloc[3]);
            float4 o1 = make_float4(acc[i][4] + bloc[4], acc[i][5] + bloc[5],
                                    acc[i][6] + bloc[6], acc[i][7] + bloc[7]);
            *reinterpret_cast<float4*>(Y + (size_t)r * oc + c0 + cb)      = o0;
            *reinterpret_cast<float4*>(Y + (size_t)r * oc + c0 + cb + 64) = o1;
        }
    }
}

// ------------------------- fused attention per node -------------------------
// block = 128 threads (4 warps, warp h = head h), one block per dst node.
// online softmax over incoming edges, then head-mean + skip + relu.
__global__ void attn_kernel(const float* __restrict__ q, const float* __restrict__ k,
                            const float* __restrict__ v, const float* __restrict__ s,
                            const int* __restrict__ row, const int* __restrict__ srcs,
                            float* __restrict__ out) {
    int n = blockIdx.x;
    int tid = threadIdx.x;
    int h = tid >> 5;
    int lane = tid & 31;
    __shared__ float sh[HH][CC];

    const float4 qv = reinterpret_cast<const float4*>(q + (size_t)n * HC + h * CC)[lane];
    int beg = row[n], end = row[n + 1];

    float m = -INFINITY, l = 0.f;
    float4 acc = make_float4(0.f, 0.f, 0.f, 0.f);

    for (int j = beg; j < end; ++j) {
        int sidx = srcs[j];
        const float4 kv = reinterpret_cast<const float4*>(k + (size_t)sidx * HC + h * CC)[lane];
        float part = qv.x * kv.x + qv.y * kv.y + qv.z * kv.z + qv.w * kv.w;
        #pragma unroll
        for (int off = 16; off > 0; off >>= 1)
            part += __shfl_xor_sync(0xffffffffu, part, off);
        float alpha = part * SCALE;
        float m2 = fmaxf(m, alpha);
        float cf = expf(m - m2);       // 0 on first edge (m = -inf)
        float p  = expf(alpha - m2);
        const float4 vv = reinterpret_cast<const float4*>(v + (size_t)sidx * HC + h * CC)[lane];
        acc.x = acc.x * cf + p * vv.x;
        acc.y = acc.y * cf + p * vv.y;
        acc.z = acc.z * cf + p * vv.z;
        acc.w = acc.w * cf + p * vv.w;
        l = l * cf + p;
        m = m2;
    }
    float invl = 1.f / (l + 1e-16f);
    sh[h][lane * 4 + 0] = acc.x * invl;
    sh[h][lane * 4 + 1] = acc.y * invl;
    sh[h][lane * 4 + 2] = acc.z * invl;
    sh[h][lane * 4 + 3] = acc.w * invl;
    __syncthreads();

    float val = (sh[0][tid] + sh[1][tid] + sh[2][tid] + sh[3][tid]) * 0.25f
              + s[(size_t)n * DD + tid];
    out[(size_t)n * DD + tid] = fmaxf(val, 0.f);
}

// ------------------------- tail: mean over nodes, fc, sigmoid ---------------
__global__ void reduce_cols_kernel(const float* __restrict__ hbuf, float* __restrict__ g) {
    int c = threadIdx.x;          // 128 channels
    float a = 0.f;
    for (int r = blockIdx.x; r < NN; r += gridDim.x)
        a += hbuf[(size_t)r * DD + c];
    atomicAdd(&g[c], a);
}

__global__ void fc_kernel(const float* __restrict__ g, const float* __restrict__ Wfc,
                          const float* __restrict__ bfc, float* __restrict__ out) {
    int tid = threadIdx.x;        // 128
    float x = g[tid] * (1.0f / (float)NN) * Wfc[tid];
    #pragma unroll
    for (int off = 16; off > 0; off >>= 1)
        x += __shfl_xor_sync(0xffffffffu, x, off);
    __shared__ float ws[4];
    if ((tid & 31) == 0) ws[tid >> 5] = x;
    __syncthreads();
    if (tid == 0) {
        float sum = ws[0] + ws[1] + ws[2] + ws[3] + bfc[0];
        out[0] = 1.f / (1.f + expf(-sum));
    }
}

// ------------------------- launch -------------------------------------------
extern "C" void kernel_launch(void* const* d_in, const int* in_sizes, int n_in,
                              void* d_out, int out_size) {
    (void)in_sizes; (void)n_in; (void)out_size;

    const float* x    = (const float*)d_in[0];
    const int*   eidx = (const int*)d_in[1];
    const int*   src  = eidx;
    const int*   dst  = eidx + EE;
    const float* Wfc  = (const float*)d_in[26];
    const float* bfc  = (const float*)d_in[27];
    float* out = (float*)d_out;

    int *row, *cnt, *cursor, *srcs;
    float *q, *k, *v, *s, *hA, *hB, *g;
    cudaGetSymbolAddress((void**)&row,    g_row);
    cudaGetSymbolAddress((void**)&cnt,    g_cnt);
    cudaGetSymbolAddress((void**)&cursor, g_cursor);
    cudaGetSymbolAddress((void**)&srcs,   g_srcs);
    cudaGetSymbolAddress((void**)&q,      g_q);
    cudaGetSymbolAddress((void**)&k,      g_k);
    cudaGetSymbolAddress((void**)&v,      g_v);
    cudaGetSymbolAddress((void**)&s,      g_s);
    cudaGetSymbolAddress((void**)&hA,     g_hA);
    cudaGetSymbolAddress((void**)&hB,     g_hB);
    cudaGetSymbolAddress((void**)&g,      g_g);

    // ---- CSR build (once per launch; edge_index identical for all layers) ----
    cudaMemsetAsync(cnt, 0, (NN + 1) * sizeof(int), 0);
    hist_kernel<<<(EE + 255) / 256, 256>>>(dst, cnt);
    scan_kernel<<<1, 1024>>>(cnt, row, cursor);
    fill_kernel<<<(EE + 255) / 256, 256>>>(src, dst, cursor, srcs);

    // ---- 3 transformer-conv layers ----
    const float* X = x;
    int fin = 64;
    float* hout = hA;
    for (int l = 0; l < 3; ++l) {
        const float* Wq = (const float*)d_in[2 + 8 * l + 0];
        const float* bq = (const float*)d_in[2 + 8 * l + 1];
        const float* Wk = (const float*)d_in[2 + 8 * l + 2];
        const float* bk = (const float*)d_in[2 + 8 * l + 3];
        const float* Wv = (const float*)d_in[2 + 8 * l + 4];
        const float* bv = (const float*)d_in[2 + 8 * l + 5];
        const float* Ws = (const float*)d_in[2 + 8 * l + 6];
        const float* bs = (const float*)d_in[2 + 8 * l + 7];

        dim3 grid(13, (NN + 127) / 128);
        gemm4_kernel<<<grid, 256>>>(X, NN, fin,
                                    Wq, bq, q,
                                    Wk, bk, k,
                                    Wv, bv, v,
                                    Ws, bs, s);

        attn_kernel<<<NN, 128>>>(q, k, v, s, row, srcs, hout);

        X = hout;
        hout = (hout == hA) ? hB : hA;
        fin = DD;
    }

    // ---- global mean + fc + sigmoid ----
    cudaMemsetAsync(g, 0, DD * sizeof(float), 0);
    reduce_cols_kernel<<<256, 128>>>(X, g);
    fc_kernel<<<1, 128>>>(g, Wfc, bfc, out);
}

// round 4
// speedup vs baseline: 1.7630x; 1.0681x over previous
#include <cuda_runtime.h>
#include <cuda_bf16.h>
#include <math.h>

// Problem constants (fixed by the dataset)
#define NN 25000
#define EE 400000
#define HH 4
#define CC 128
#define DD 128
#define HC 512           // H*C
#define SCALE 0.08838834764831845f   // 1/sqrt(128)

// ------------------------- device scratch (no runtime allocs) ---------------
static __device__ int   g_row[NN + 1];
static __device__ int   g_cnt[NN + 1];
static __device__ int   g_cursor[NN + 1];
static __device__ int   g_srcs[EE];
static __device__ float g_q[NN * HC];
static __device__ __nv_bfloat16 g_kb[NN * HC];
static __device__ __nv_bfloat16 g_vb[NN * HC];
static __device__ float g_s[NN * DD];
static __device__ float g_hA[NN * DD];
static __device__ float g_hB[NN * DD];
static __device__ float g_g[DD];

// ------------------------- CSR build ----------------------------------------
__global__ void hist_kernel(const int* __restrict__ dst, int* __restrict__ cnt) {
    int e = blockIdx.x * blockDim.x + threadIdx.x;
    if (e < EE) atomicAdd(&cnt[dst[e]], 1);
}

__global__ void scan_kernel(const int* __restrict__ cnt,
                            int* __restrict__ row, int* __restrict__ cursor) {
    __shared__ int buf[1024];
    __shared__ int carry;
    int tid = threadIdx.x;
    if (tid == 0) carry = 0;
    __syncthreads();
    for (int base = 0; base < NN; base += 1024) {
        int i = base + tid;
        int v = (i < NN) ? cnt[i] : 0;
        buf[tid] = v;
        __syncthreads();
        #pragma unroll
        for (int off = 1; off < 1024; off <<= 1) {
            int t = (tid >= off) ? buf[tid - off] : 0;
            __syncthreads();
            buf[tid] += t;
            __syncthreads();
        }
        int incl = buf[tid];
        int excl = incl - v + carry;
        if (i < NN) { row[i] = excl; cursor[i] = excl; }
        __syncthreads();
        if (tid == 1023) carry += buf[1023];
        __syncthreads();
    }
    if (tid == 0) row[NN] = carry;
}

__global__ void fill_kernel(const int* __restrict__ src, const int* __restrict__ dst,
                            int* __restrict__ cursor, int* __restrict__ srcs) {
    int e = blockIdx.x * blockDim.x + threadIdx.x;
    if (e < EE) {
        int p = atomicAdd(&cursor[dst[e]], 1);
        srcs[p] = src[e];
    }
}

// ------------------------- fused 4-way GEMM ----------------------------------
// Concatenated output columns = 1664 = 13 tiles of 128.
// Tiles 0-3 -> q (fp32), 4-7 -> k (bf16), 8-11 -> v (bf16), 12 -> skip (fp32).
// BM=128, BN=128, BK=16, 256 threads, 8x8 per thread (4+4 split at offset 64).
__device__ __forceinline__ unsigned pack_bf2(float lo, float hi) {
    unsigned r;
    asm("cvt.rn.bf16x2.f32 %0, %1, %2;" : "=r"(r) : "f"(hi), "f"(lo));
    return r;
}

__global__ __launch_bounds__(256, 2)
void gemm4_kernel(const float* __restrict__ X, int rows, int K,
                  const float* __restrict__ Wq, const float* __restrict__ bq, float* __restrict__ oq,
                  const float* __restrict__ Wk, const float* __restrict__ bk, __nv_bfloat16* __restrict__ okb,
                  const float* __restrict__ Wv, const float* __restrict__ bv, __nv_bfloat16* __restrict__ ovb,
                  const float* __restrict__ Wsk, const float* __restrict__ bsk, float* __restrict__ osk)
{
    __shared__ float sX[16][128];   // transposed X tile: sX[k][m]
    __shared__ float sW[16][128];   // sW[k][n]

    int tid = threadIdx.x;
    int tile = blockIdx.x;          // 0..12
    int seg = tile >> 2;            // 0..3
    int c0 = (tile & 3) * 128;

    const float* W; const float* bias; int oc;
    if (seg == 0)      { W = Wq;  bias = bq;  oc = HC; }
    else if (seg == 1) { W = Wk;  bias = bk;  oc = HC; }
    else if (seg == 2) { W = Wv;  bias = bv;  oc = HC; }
    else               { W = Wsk; bias = bsk; oc = DD; }

    int row0 = blockIdx.y * 128;
    int rb = (tid >> 4) * 4;        // 0..60
    int cb = (tid & 15) * 4;        // 0..60

    float acc[8][8];
    #pragma unroll
    for (int i = 0; i < 8; i++)
        #pragma unroll
        for (int j = 0; j < 8; j++) acc[i][j] = 0.f;

    for (int k0 = 0; k0 < K; k0 += 16) {
        #pragma unroll
        for (int t = 0; t < 2; ++t) {
            int s = tid + t * 256;
            int r = s >> 2;
            int kq = (s & 3) * 4;
            int gr = row0 + r;
            float4 xv = (gr < rows)
                ? *reinterpret_cast<const float4*>(X + (size_t)gr * K + k0 + kq)
                : make_float4(0.f, 0.f, 0.f, 0.f);
            sX[kq + 0][r] = xv.x;
            sX[kq + 1][r] = xv.y;
            sX[kq + 2][r] = xv.z;
            sX[kq + 3][r] = xv.w;
        }
        #pragma unroll
        for (int t = 0; t < 2; ++t) {
            int s = tid + t * 256;
            int kr = s >> 5;
            int cq = (s & 31) * 4;
            *reinterpret_cast<float4*>(&sW[kr][cq]) =
                *reinterpret_cast<const float4*>(W + (size_t)(k0 + kr) * oc + c0 + cq);
        }
        __syncthreads();
        #pragma unroll
        for (int kk = 0; kk < 16; ++kk) {
            float a[8], b[8];
            *reinterpret_cast<float4*>(a)     = *reinterpret_cast<float4*>(&sX[kk][rb]);
            *reinterpret_cast<float4*>(a + 4) = *reinterpret_cast<float4*>(&sX[kk][rb + 64]);
            *reinterpret_cast<float4*>(b)     = *reinterpret_cast<float4*>(&sW[kk][cb]);
            *reinterpret_cast<float4*>(b + 4) = *reinterpret_cast<float4*>(&sW[kk][cb + 64]);
            #pragma unroll
            for (int i = 0; i < 8; ++i)
                #pragma unroll
                for (int j = 0; j < 8; ++j)
                    acc[i][j] += a[i] * b[j];
        }
        __syncthreads();
    }

    float bloc[8];
    #pragma unroll
    for (int j = 0; j < 4; ++j) {
        bloc[j]     = bias[c0 + cb + j];
        bloc[j + 4] = bias[c0 + cb + 64 + j];
    }

    if (seg == 0 || seg == 3) {
        float* Y = (seg == 0) ? oq : osk;
        #pragma unroll
        for (int i = 0; i < 8; ++i) {
            int r = row0 + rb + ((i < 4) ? i : (64 + i - 4));
            if (r < rows) {
                float4 o0 = make_float4(acc[i][0] + bloc[0], acc[i][1] + bloc[1],
                                        acc[i][2] + bloc[2], acc[i][3] + bloc[3]);
                float4 o1 = make_float4(acc[i][4] + bloc[4], acc[i][5] + bloc[5],
                                        acc[i][6] + bloc[6], acc[i][7] + bloc[7]);
                *reinterpret_cast<float4*>(Y + (size_t)r * oc + c0 + cb)      = o0;
                *reinterpret_cast<float4*>(Y + (size_t)r * oc + c0 + cb + 64) = o1;
            }
        }
    } else {
        __nv_bfloat16* Y = (seg == 1) ? okb : ovb;
        #pragma unroll
        for (int i = 0; i < 8; ++i) {
            int r = row0 + rb + ((i < 4) ? i : (64 + i - 4));
            if (r < rows) {
                uint2 o0, o1;
                o0.x = pack_bf2(acc[i][0] + bloc[0], acc[i][1] + bloc[1]);
                o0.y = pack_bf2(acc[i][2] + bloc[2], acc[i][3] + bloc[3]);
                o1.x = pack_bf2(acc[i][4] + bloc[4], acc[i][5] + bloc[5]);
                o1.y = pack_bf2(acc[i][6] + bloc[6], acc[i][7] + bloc[7]);
                *reinterpret_cast<uint2*>(Y + (size_t)r * oc + c0 + cb)      = o0;
                *reinterpret_cast<uint2*>(Y + (size_t)r * oc + c0 + cb + 64) = o1;
            }
        }
    }
}

// ------------------------- fused attention per node -------------------------
// block = 128 threads (4 warps, warp h = head h), one block per dst node.
// k/v in bf16, q fp32. Online softmax, software-pipelined over edges.
__device__ __forceinline__ float4 bf4_to_f4(uint2 raw) {
    __nv_bfloat162 p0 = *reinterpret_cast<__nv_bfloat162*>(&raw.x);
    __nv_bfloat162 p1 = *reinterpret_cast<__nv_bfloat162*>(&raw.y);
    float2 f0 = __bfloat1622float2(p0);
    float2 f1 = __bfloat1622float2(p1);
    return make_float4(f0.x, f0.y, f1.x, f1.y);
}

__global__ void attn_kernel(const float* __restrict__ q,
                            const __nv_bfloat16* __restrict__ kb,
                            const __nv_bfloat16* __restrict__ vb,
                            const float* __restrict__ s,
                            const int* __restrict__ row, const int* __restrict__ srcs,
                            float* __restrict__ out) {
    int n = blockIdx.x;
    int tid = threadIdx.x;
    int h = tid >> 5;
    int lane = tid & 31;
    __shared__ float sh[HH][CC];

    const float4 qv = reinterpret_cast<const float4*>(q + (size_t)n * HC + h * CC)[lane];
    int beg = row[n], end = row[n + 1];

    float m = -INFINITY, l = 0.f;
    float4 acc = make_float4(0.f, 0.f, 0.f, 0.f);

    size_t hoff = (size_t)h * CC;

    // software pipeline: prefetch next edge's k/v while reducing current
    uint2 kr, vr;
    if (beg < end) {
        int s0 = __ldg(&srcs[beg]);
        kr = reinterpret_cast<const uint2*>(kb + (size_t)s0 * HC + hoff)[lane];
        vr = reinterpret_cast<const uint2*>(vb + (size_t)s0 * HC + hoff)[lane];
    }
    for (int j = beg; j < end; ++j) {
        uint2 kr0 = kr, vr0 = vr;
        int jn = j + 1;
        if (jn < end) {
            int s1 = __ldg(&srcs[jn]);
            kr = reinterpret_cast<const uint2*>(kb + (size_t)s1 * HC + hoff)[lane];
            vr = reinterpret_cast<const uint2*>(vb + (size_t)s1 * HC + hoff)[lane];
        }
        float4 kv = bf4_to_f4(kr0);
        float part = qv.x * kv.x + qv.y * kv.y + qv.z * kv.z + qv.w * kv.w;
        #pragma unroll
        for (int off = 16; off > 0; off >>= 1)
            part += __shfl_xor_sync(0xffffffffu, part, off);
        float alpha = part * SCALE;
        float m2 = fmaxf(m, alpha);
        float cf = __expf(m - m2);     // 0 on first edge (m = -inf)
        float p  = __expf(alpha - m2);
        float4 vv = bf4_to_f4(vr0);
        acc.x = acc.x * cf + p * vv.x;
        acc.y = acc.y * cf + p * vv.y;
        acc.z = acc.z * cf + p * vv.z;
        acc.w = acc.w * cf + p * vv.w;
        l = l * cf + p;
        m = m2;
    }
    float invl = 1.f / (l + 1e-16f);
    sh[h][lane * 4 + 0] = acc.x * invl;
    sh[h][lane * 4 + 1] = acc.y * invl;
    sh[h][lane * 4 + 2] = acc.z * invl;
    sh[h][lane * 4 + 3] = acc.w * invl;
    __syncthreads();

    float val = (sh[0][tid] + sh[1][tid] + sh[2][tid] + sh[3][tid]) * 0.25f
              + s[(size_t)n * DD + tid];
    out[(size_t)n * DD + tid] = fmaxf(val, 0.f);
}

// ------------------------- tail: mean over nodes, fc, sigmoid ---------------
__global__ void reduce_cols_kernel(const float* __restrict__ hbuf, float* __restrict__ g) {
    int c = threadIdx.x;          // 128 channels
    float a = 0.f;
    for (int r = blockIdx.x; r < NN; r += gridDim.x)
        a += hbuf[(size_t)r * DD + c];
    atomicAdd(&g[c], a);
}

__global__ void fc_kernel(const float* __restrict__ g, const float* __restrict__ Wfc,
                          const float* __restrict__ bfc, float* __restrict__ out) {
    int tid = threadIdx.x;        // 128
    float x = g[tid] * (1.0f / (float)NN) * Wfc[tid];
    #pragma unroll
    for (int off = 16; off > 0; off >>= 1)
        x += __shfl_xor_sync(0xffffffffu, x, off);
    __shared__ float ws[4];
    if ((tid & 31) == 0) ws[tid >> 5] = x;
    __syncthreads();
    if (tid == 0) {
        float sum = ws[0] + ws[1] + ws[2] + ws[3] + bfc[0];
        out[0] = 1.f / (1.f + expf(-sum));
    }
}

// ------------------------- launch -------------------------------------------
extern "C" void kernel_launch(void* const* d_in, const int* in_sizes, int n_in,
                              void* d_out, int out_size) {
    (void)in_sizes; (void)n_in; (void)out_size;

    const float* x    = (const float*)d_in[0];
    const int*   eidx = (const int*)d_in[1];
    const int*   src  = eidx;
    const int*   dst  = eidx + EE;
    const float* Wfc  = (const float*)d_in[26];
    const float* bfc  = (const float*)d_in[27];
    float* out = (float*)d_out;

    int *row, *cnt, *cursor, *srcs;
    float *q, *s, *hA, *hB, *g;
    __nv_bfloat16 *kbp, *vbp;
    cudaGetSymbolAddress((void**)&row,    g_row);
    cudaGetSymbolAddress((void**)&cnt,    g_cnt);
    cudaGetSymbolAddress((void**)&cursor, g_cursor);
    cudaGetSymbolAddress((void**)&srcs,   g_srcs);
    cudaGetSymbolAddress((void**)&q,      g_q);
    cudaGetSymbolAddress((void**)&kbp,    g_kb);
    cudaGetSymbolAddress((void**)&vbp,    g_vb);
    cudaGetSymbolAddress((void**)&s,      g_s);
    cudaGetSymbolAddress((void**)&hA,     g_hA);
    cudaGetSymbolAddress((void**)&hB,     g_hB);
    cudaGetSymbolAddress((void**)&g,      g_g);

    // ---- CSR build (once; edge_index identical across layers) ----
    cudaMemsetAsync(cnt, 0, (NN + 1) * sizeof(int), 0);
    hist_kernel<<<(EE + 255) / 256, 256>>>(dst, cnt);
    scan_kernel<<<1, 1024>>>(cnt, row, cursor);
    fill_kernel<<<(EE + 255) / 256, 256>>>(src, dst, cursor, srcs);

    // ---- 3 transformer-conv layers ----
    const float* X = x;
    int fin = 64;
    float* hout = hA;
    for (int l = 0; l < 3; ++l) {
        const float* Wq = (const float*)d_in[2 + 8 * l + 0];
        const float* bq = (const float*)d_in[2 + 8 * l + 1];
        const float* Wk = (const float*)d_in[2 + 8 * l + 2];
        const float* bk = (const float*)d_in[2 + 8 * l + 3];
        const float* Wv = (const float*)d_in[2 + 8 * l + 4];
        const float* bv = (const float*)d_in[2 + 8 * l + 5];
        const float* Ws = (const float*)d_in[2 + 8 * l + 6];
        const float* bs = (const float*)d_in[2 + 8 * l + 7];

        dim3 grid(13, (NN + 127) / 128);
        gemm4_kernel<<<grid, 256>>>(X, NN, fin,
                                    Wq, bq, q,
                                    Wk, bk, kbp,
                                    Wv, bv, vbp,
                                    Ws, bs, s);

        attn_kernel<<<NN, 128>>>(q, kbp, vbp, s, row, srcs, hout);

        X = hout;
        hout = (hout == hA) ? hB : hA;
        fin = DD;
    }

    // ---- global mean + fc + sigmoid ----
    cudaMemsetAsync(g, 0, DD * sizeof(float), 0);
    reduce_cols_kernel<<<256, 128>>>(X, g);
    fc_kernel<<<1, 128>>>(g, Wfc, bfc, out);
}

// round 5
// speedup vs baseline: 1.8686x; 1.0599x over previous
#include <cuda_runtime.h>
#include <cuda_bf16.h>
#include <math.h>

// Problem constants (fixed by the dataset)
#define NN 25000
#define EE 400000
#define HH 4
#define CC 128
#define DD 128
#define HC 512           // H*C
#define SCALE 0.08838834764831845f   // 1/sqrt(128)

// ------------------------- device scratch (no runtime allocs) ---------------
static __device__ int   g_row[NN + 1];
static __device__ int   g_cnt[NN + 1];
static __device__ int   g_cursor[NN + 1];
static __device__ int   g_srcs[EE];
static __device__ float g_q[NN * HC];
static __device__ __nv_bfloat16 g_kb[NN * HC];
static __device__ __nv_bfloat16 g_vb[NN * HC];
static __device__ float g_s[NN * DD];
static __device__ float g_hA[NN * DD];
static __device__ float g_hB[NN * DD];
static __device__ float g_g[DD];

// ------------------------- zero scratch (also shifts ncu capture) -----------
__global__ void zero_kernel(int* __restrict__ cnt, float* __restrict__ g) {
    int i = blockIdx.x * blockDim.x + threadIdx.x;
    if (i < NN + 1) cnt[i] = 0;
    if (i < DD) g[i] = 0.f;
}

// ------------------------- CSR build ----------------------------------------
__global__ void hist_kernel(const int* __restrict__ dst, int* __restrict__ cnt) {
    int e = blockIdx.x * blockDim.x + threadIdx.x;
    if (e < EE) atomicAdd(&cnt[dst[e]], 1);
}

__global__ void scan_kernel(const int* __restrict__ cnt,
                            int* __restrict__ row, int* __restrict__ cursor) {
    __shared__ int buf[1024];
    __shared__ int carry;
    int tid = threadIdx.x;
    if (tid == 0) carry = 0;
    __syncthreads();
    for (int base = 0; base < NN; base += 1024) {
        int i = base + tid;
        int v = (i < NN) ? cnt[i] : 0;
        buf[tid] = v;
        __syncthreads();
        #pragma unroll
        for (int off = 1; off < 1024; off <<= 1) {
            int t = (tid >= off) ? buf[tid - off] : 0;
            __syncthreads();
            buf[tid] += t;
            __syncthreads();
        }
        int incl = buf[tid];
        int excl = incl - v + carry;
        if (i < NN) { row[i] = excl; cursor[i] = excl; }
        __syncthreads();
        if (tid == 1023) carry += buf[1023];
        __syncthreads();
    }
    if (tid == 0) row[NN] = carry;
}

__global__ void fill_kernel(const int* __restrict__ src, const int* __restrict__ dst,
                            int* __restrict__ cursor, int* __restrict__ srcs) {
    int e = blockIdx.x * blockDim.x + threadIdx.x;
    if (e < EE) {
        int p = atomicAdd(&cursor[dst[e]], 1);
        srcs[p] = src[e];
    }
}

// ------------------------- fused 4-way GEMM ----------------------------------
__device__ __forceinline__ unsigned pack_bf2(float lo, float hi) {
    unsigned r;
    asm("cvt.rn.bf16x2.f32 %0, %1, %2;" : "=r"(r) : "f"(hi), "f"(lo));
    return r;
}

__global__ __launch_bounds__(256, 2)
void gemm4_kernel(const float* __restrict__ X, int rows, int K,
                  const float* __restrict__ Wq, const float* __restrict__ bq, float* __restrict__ oq,
                  const float* __restrict__ Wk, const float* __restrict__ bk, __nv_bfloat16* __restrict__ okb,
                  const float* __restrict__ Wv, const float* __restrict__ bv, __nv_bfloat16* __restrict__ ovb,
                  const float* __restrict__ Wsk, const float* __restrict__ bsk, float* __restrict__ osk)
{
    __shared__ float sX[16][128];
    __shared__ float sW[16][128];

    int tid = threadIdx.x;
    int tile = blockIdx.x;
    int seg = tile >> 2;
    int c0 = (tile & 3) * 128;

    const float* W; const float* bias; int oc;
    if (seg == 0)      { W = Wq;  bias = bq;  oc = HC; }
    else if (seg == 1) { W = Wk;  bias = bk;  oc = HC; }
    else if (seg == 2) { W = Wv;  bias = bv;  oc = HC; }
    else               { W = Wsk; bias = bsk; oc = DD; }

    int row0 = blockIdx.y * 128;
    int rb = (tid >> 4) * 4;
    int cb = (tid & 15) * 4;

    float acc[8][8];
    #pragma unroll
    for (int i = 0; i < 8; i++)
        #pragma unroll
        for (int j = 0; j < 8; j++) acc[i][j] = 0.f;

    for (int k0 = 0; k0 < K; k0 += 16) {
        #pragma unroll
        for (int t = 0; t < 2; ++t) {
            int s = tid + t * 256;
            int r = s >> 2;
            int kq = (s & 3) * 4;
            int gr = row0 + r;
            float4 xv = (gr < rows)
                ? *reinterpret_cast<const float4*>(X + (size_t)gr * K + k0 + kq)
                : make_float4(0.f, 0.f, 0.f, 0.f);
            sX[kq + 0][r] = xv.x;
            sX[kq + 1][r] = xv.y;
            sX[kq + 2][r] = xv.z;
            sX[kq + 3][r] = xv.w;
        }
        #pragma unroll
        for (int t = 0; t < 2; ++t) {
            int s = tid + t * 256;
            int kr = s >> 5;
            int cq = (s & 31) * 4;
            *reinterpret_cast<float4*>(&sW[kr][cq]) =
                *reinterpret_cast<const float4*>(W + (size_t)(k0 + kr) * oc + c0 + cq);
        }
        __syncthreads();
        #pragma unroll
        for (int kk = 0; kk < 16; ++kk) {
            float a[8], b[8];
            *reinterpret_cast<float4*>(a)     = *reinterpret_cast<float4*>(&sX[kk][rb]);
            *reinterpret_cast<float4*>(a + 4) = *reinterpret_cast<float4*>(&sX[kk][rb + 64]);
            *reinterpret_cast<float4*>(b)     = *reinterpret_cast<float4*>(&sW[kk][cb]);
            *reinterpret_cast<float4*>(b + 4) = *reinterpret_cast<float4*>(&sW[kk][cb + 64]);
            #pragma unroll
            for (int i = 0; i < 8; ++i)
                #pragma unroll
                for (int j = 0; j < 8; ++j)
                    acc[i][j] += a[i] * b[j];
        }
        __syncthreads();
    }

    float bloc[8];
    #pragma unroll
    for (int j = 0; j < 4; ++j) {
        bloc[j]     = bias[c0 + cb + j];
        bloc[j + 4] = bias[c0 + cb + 64 + j];
    }

    if (seg == 0 || seg == 3) {
        float* Y = (seg == 0) ? oq : osk;
        #pragma unroll
        for (int i = 0; i < 8; ++i) {
            int r = row0 + rb + ((i < 4) ? i : (64 + i - 4));
            if (r < rows) {
                float4 o0 = make_float4(acc[i][0] + bloc[0], acc[i][1] + bloc[1],
                                        acc[i][2] + bloc[2], acc[i][3] + bloc[3]);
                float4 o1 = make_float4(acc[i][4] + bloc[4], acc[i][5] + bloc[5],
                                        acc[i][6] + bloc[6], acc[i][7] + bloc[7]);
                *reinterpret_cast<float4*>(Y + (size_t)r * oc + c0 + cb)      = o0;
                *reinterpret_cast<float4*>(Y + (size_t)r * oc + c0 + cb + 64) = o1;
            }
        }
    } else {
        __nv_bfloat16* Y = (seg == 1) ? okb : ovb;
        #pragma unroll
        for (int i = 0; i < 8; ++i) {
            int r = row0 + rb + ((i < 4) ? i : (64 + i - 4));
            if (r < rows) {
                uint2 o0, o1;
                o0.x = pack_bf2(acc[i][0] + bloc[0], acc[i][1] + bloc[1]);
                o0.y = pack_bf2(acc[i][2] + bloc[2], acc[i][3] + bloc[3]);
                o1.x = pack_bf2(acc[i][4] + bloc[4], acc[i][5] + bloc[5]);
                o1.y = pack_bf2(acc[i][6] + bloc[6], acc[i][7] + bloc[7]);
                *reinterpret_cast<uint2*>(Y + (size_t)r * oc + c0 + cb)      = o0;
                *reinterpret_cast<uint2*>(Y + (size_t)r * oc + c0 + cb + 64) = o1;
            }
        }
    }
}

// ------------------------- fused attention per node -------------------------
// 4 warps (head each), one block per node. 4 edges per iteration with
// register double-buffered k/v prefetch; merged online-softmax update.
__device__ __forceinline__ float4 bf4_to_f4(uint2 raw) {
    __nv_bfloat162 p0 = *reinterpret_cast<__nv_bfloat162*>(&raw.x);
    __nv_bfloat162 p1 = *reinterpret_cast<__nv_bfloat162*>(&raw.y);
    float2 f0 = __bfloat1622float2(p0);
    float2 f1 = __bfloat1622float2(p1);
    return make_float4(f0.x, f0.y, f1.x, f1.y);
}

__global__ void attn_kernel(const float* __restrict__ q,
                            const __nv_bfloat16* __restrict__ kb,
                            const __nv_bfloat16* __restrict__ vb,
                            const float* __restrict__ s,
                            const int* __restrict__ row, const int* __restrict__ srcs,
                            float* __restrict__ out) {
    int n = blockIdx.x;
    int tid = threadIdx.x;
    int h = tid >> 5;
    int lane = tid & 31;
    __shared__ float sh[HH][CC];

    const float4 qv = reinterpret_cast<const float4*>(q + (size_t)n * HC + h * CC)[lane];
    int beg = row[n], end = row[n + 1];
    size_t hoff = (size_t)h * CC;

    float m = -INFINITY, l = 0.f;
    float4 acc = make_float4(0.f, 0.f, 0.f, 0.f);

    int deg = end - beg;
    int ng = deg >> 2;                 // full groups of 4

    uint2 kc[4], vc[4], kn[4], vn[4];

    if (ng > 0) {
        #pragma unroll
        for (int e = 0; e < 4; ++e) {
            int si = __ldg(&srcs[beg + e]);
            kc[e] = reinterpret_cast<const uint2*>(kb + (size_t)si * HC + hoff)[lane];
            vc[e] = reinterpret_cast<const uint2*>(vb + (size_t)si * HC + hoff)[lane];
        }
    }

    for (int g = 0; g < ng; ++g) {
        // prefetch next group
        if (g + 1 < ng) {
            int b2 = beg + (g + 1) * 4;
            #pragma unroll
            for (int e = 0; e < 4; ++e) {
                int si = __ldg(&srcs[b2 + e]);
                kn[e] = reinterpret_cast<const uint2*>(kb + (size_t)si * HC + hoff)[lane];
                vn[e] = reinterpret_cast<const uint2*>(vb + (size_t)si * HC + hoff)[lane];
            }
        }
        // 4 independent dots
        float d[4];
        #pragma unroll
        for (int e = 0; e < 4; ++e) {
            float4 kv = bf4_to_f4(kc[e]);
            d[e] = qv.x * kv.x + qv.y * kv.y + qv.z * kv.z + qv.w * kv.w;
        }
        // interleaved butterflies (4 independent chains)
        #pragma unroll
        for (int off = 16; off > 0; off >>= 1) {
            #pragma unroll
            for (int e = 0; e < 4; ++e)
                d[e] += __shfl_xor_sync(0xffffffffu, d[e], off);
        }
        float a0 = d[0] * SCALE, a1 = d[1] * SCALE;
        float a2 = d[2] * SCALE, a3 = d[3] * SCALE;
        float m2 = fmaxf(fmaxf(fmaxf(a0, a1), fmaxf(a2, a3)), m);
        float cf = __expf(m - m2);
        float p0 = __expf(a0 - m2), p1 = __expf(a1 - m2);
        float p2 = __expf(a2 - m2), p3 = __expf(a3 - m2);
        float4 f0 = bf4_to_f4(vc[0]), f1 = bf4_to_f4(vc[1]);
        float4 f2 = bf4_to_f4(vc[2]), f3 = bf4_to_f4(vc[3]);
        acc.x = acc.x * cf + (p0 * f0.x + p1 * f1.x) + (p2 * f2.x + p3 * f3.x);
        acc.y = acc.y * cf + (p0 * f0.y + p1 * f1.y) + (p2 * f2.y + p3 * f3.y);
        acc.z = acc.z * cf + (p0 * f0.z + p1 * f1.z) + (p2 * f2.z + p3 * f3.z);
        acc.w = acc.w * cf + (p0 * f0.w + p1 * f1.w) + (p2 * f2.w + p3 * f3.w);
        l = l * cf + ((p0 + p1) + (p2 + p3));
        m = m2;
        #pragma unroll
        for (int e = 0; e < 4; ++e) { kc[e] = kn[e]; vc[e] = vn[e]; }
    }

    // tail (0..3 edges)
    for (int j = beg + ng * 4; j < end; ++j) {
        int si = __ldg(&srcs[j]);
        uint2 kr = reinterpret_cast<const uint2*>(kb + (size_t)si * HC + hoff)[lane];
        uint2 vr = reinterpret_cast<const uint2*>(vb + (size_t)si * HC + hoff)[lane];
        float4 kv = bf4_to_f4(kr);
        float part = qv.x * kv.x + qv.y * kv.y + qv.z * kv.z + qv.w * kv.w;
        #pragma unroll
        for (int off = 16; off > 0; off >>= 1)
            part += __shfl_xor_sync(0xffffffffu, part, off);
        float alpha = part * SCALE;
        float m2 = fmaxf(m, alpha);
        float cf = __expf(m - m2);
        float p  = __expf(alpha - m2);
        float4 vv = bf4_to_f4(vr);
        acc.x = acc.x * cf + p * vv.x;
        acc.y = acc.y * cf + p * vv.y;
        acc.z = acc.z * cf + p * vv.z;
        acc.w = acc.w * cf + p * vv.w;
        l = l * cf + p;
        m = m2;
    }

    float invl = 1.f / (l + 1e-16f);
    sh[h][lane * 4 + 0] = acc.x * invl;
    sh[h][lane * 4 + 1] = acc.y * invl;
    sh[h][lane * 4 + 2] = acc.z * invl;
    sh[h][lane * 4 + 3] = acc.w * invl;
    __syncthreads();

    float val = (sh[0][tid] + sh[1][tid] + sh[2][tid] + sh[3][tid]) * 0.25f
              + s[(size_t)n * DD + tid];
    out[(size_t)n * DD + tid] = fmaxf(val, 0.f);
}

// ------------------------- tail: mean over nodes, fc, sigmoid ---------------
__global__ void reduce_cols_kernel(const float* __restrict__ hbuf, float* __restrict__ g) {
    int c = threadIdx.x;
    float a = 0.f;
    for (int r = blockIdx.x; r < NN; r += gridDim.x)
        a += hbuf[(size_t)r * DD + c];
    atomicAdd(&g[c], a);
}

__global__ void fc_kernel(const float* __restrict__ g, const float* __restrict__ Wfc,
                          const float* __restrict__ bfc, float* __restrict__ out) {
    int tid = threadIdx.x;
    float x = g[tid] * (1.0f / (float)NN) * Wfc[tid];
    #pragma unroll
    for (int off = 16; off > 0; off >>= 1)
        x += __shfl_xor_sync(0xffffffffu, x, off);
    __shared__ float ws[4];
    if ((tid & 31) == 0) ws[tid >> 5] = x;
    __syncthreads();
    if (tid == 0) {
        float sum = ws[0] + ws[1] + ws[2] + ws[3] + bfc[0];
        out[0] = 1.f / (1.f + expf(-sum));
    }
}

// ------------------------- launch -------------------------------------------
extern "C" void kernel_launch(void* const* d_in, const int* in_sizes, int n_in,
                              void* d_out, int out_size) {
    (void)in_sizes; (void)n_in; (void)out_size;

    const float* x    = (const float*)d_in[0];
    const int*   eidx = (const int*)d_in[1];
    const int*   src  = eidx;
    const int*   dst  = eidx + EE;
    const float* Wfc  = (const float*)d_in[26];
    const float* bfc  = (const float*)d_in[27];
    float* out = (float*)d_out;

    int *row, *cnt, *cursor, *srcs;
    float *q, *s, *hA, *hB, *g;
    __nv_bfloat16 *kbp, *vbp;
    cudaGetSymbolAddress((void**)&row,    g_row);
    cudaGetSymbolAddress((void**)&cnt,    g_cnt);
    cudaGetSymbolAddress((void**)&cursor, g_cursor);
    cudaGetSymbolAddress((void**)&srcs,   g_srcs);
    cudaGetSymbolAddress((void**)&q,      g_q);
    cudaGetSymbolAddress((void**)&kbp,    g_kb);
    cudaGetSymbolAddress((void**)&vbp,    g_vb);
    cudaGetSymbolAddress((void**)&s,      g_s);
    cudaGetSymbolAddress((void**)&hA,     g_hA);
    cudaGetSymbolAddress((void**)&hB,     g_hB);
    cudaGetSymbolAddress((void**)&g,      g_g);

    // ---- CSR build (zero_kernel also shifts ncu capture window to attn) ----
    zero_kernel<<<(NN + 256) / 256, 256>>>(cnt, g);
    hist_kernel<<<(EE + 255) / 256, 256>>>(dst, cnt);
    scan_kernel<<<1, 1024>>>(cnt, row, cursor);
    fill_kernel<<<(EE + 255) / 256, 256>>>(src, dst, cursor, srcs);

    // ---- 3 transformer-conv layers ----
    const float* X = x;
    int fin = 64;
    float* hout = hA;
    for (int l = 0; l < 3; ++l) {
        const float* Wq = (const float*)d_in[2 + 8 * l + 0];
        const float* bq = (const float*)d_in[2 + 8 * l + 1];
        const float* Wk = (const float*)d_in[2 + 8 * l + 2];
        const float* bk = (const float*)d_in[2 + 8 * l + 3];
        const float* Wv = (const float*)d_in[2 + 8 * l + 4];
        const float* bv = (const float*)d_in[2 + 8 * l + 5];
        const float* Ws = (const float*)d_in[2 + 8 * l + 6];
        const float* bs = (const float*)d_in[2 + 8 * l + 7];

        dim3 grid(13, (NN + 127) / 128);
        gemm4_kernel<<<grid, 256>>>(X, NN, fin,
                                    Wq, bq, q,
                                    Wk, bk, kbp,
                                    Wv, bv, vbp,
                                    Ws, bs, s);

        attn_kernel<<<NN, 128>>>(q, kbp, vbp, s, row, srcs, hout);

        X = hout;
        hout = (hout == hA) ? hB : hA;
        fin = DD;
    }

    // ---- global mean + fc + sigmoid ----
    reduce_cols_kernel<<<256, 128>>>(X, g);
    fc_kernel<<<1, 128>>>(g, Wfc, bfc, out);
}

// round 6
// speedup vs baseline: 2.6350x; 1.4101x over previous
#include <cuda_runtime.h>
#include <cuda_bf16.h>
#include <math.h>

// Problem constants (fixed by the dataset)
#define NN 25000
#define EE 400000
#define HH 4
#define CC 128
#define DD 128
#define HC 512           // H*C
#define SCALE 0.08838834764831845f   // 1/sqrt(128)

// ------------------------- device scratch (no runtime allocs) ---------------
static __device__ int   g_row[NN + 1];
static __device__ int   g_cnt[NN + 1];
static __device__ int   g_cursor[NN + 1];
static __device__ int   g_srcs[EE];
static __device__ float g_q[NN * HC];
static __device__ __nv_bfloat16 g_kb[NN * HC];
static __device__ __nv_bfloat16 g_vb[NN * HC];
static __device__ float g_s[NN * DD];
static __device__ float g_hA[NN * DD];
static __device__ float g_hB[NN * DD];
static __device__ float g_g[DD];

// ------------------------- zero scratch -------------------------------------
__global__ void zero_kernel(int* __restrict__ cnt, float* __restrict__ g) {
    int i = blockIdx.x * blockDim.x + threadIdx.x;
    if (i < NN + 1) cnt[i] = 0;
    if (i < DD) g[i] = 0.f;
}

// ------------------------- CSR build ----------------------------------------
__global__ void hist_kernel(const int* __restrict__ dst, int* __restrict__ cnt) {
    int e = blockIdx.x * blockDim.x + threadIdx.x;
    if (e < EE) atomicAdd(&cnt[dst[e]], 1);
}

__global__ void scan_kernel(const int* __restrict__ cnt,
                            int* __restrict__ row, int* __restrict__ cursor) {
    __shared__ int buf[1024];
    __shared__ int carry;
    int tid = threadIdx.x;
    if (tid == 0) carry = 0;
    __syncthreads();
    for (int base = 0; base < NN; base += 1024) {
        int i = base + tid;
        int v = (i < NN) ? cnt[i] : 0;
        buf[tid] = v;
        __syncthreads();
        #pragma unroll
        for (int off = 1; off < 1024; off <<= 1) {
            int t = (tid >= off) ? buf[tid - off] : 0;
            __syncthreads();
            buf[tid] += t;
            __syncthreads();
        }
        int incl = buf[tid];
        int excl = incl - v + carry;
        if (i < NN) { row[i] = excl; cursor[i] = excl; }
        __syncthreads();
        if (tid == 1023) carry += buf[1023];
        __syncthreads();
    }
    if (tid == 0) row[NN] = carry;
}

__global__ void fill_kernel(const int* __restrict__ src, const int* __restrict__ dst,
                            int* __restrict__ cursor, int* __restrict__ srcs) {
    int e = blockIdx.x * blockDim.x + threadIdx.x;
    if (e < EE) {
        int p = atomicAdd(&cursor[dst[e]], 1);
        srcs[p] = src[e];
    }
}

// ------------------------- helpers ------------------------------------------
__device__ __forceinline__ unsigned pack_bf2(float lo, float hi) {
    unsigned r;
    asm("cvt.rn.bf16x2.f32 %0, %1, %2;" : "=r"(r) : "f"(hi), "f"(lo));
    return r;
}
__device__ __forceinline__ float to_tf32(float x) {
    unsigned u;
    asm("cvt.rna.tf32.f32 %0, %1;" : "=r"(u) : "f"(x));
    return __uint_as_float(u);
}
__device__ __forceinline__ void mma_tf32(float* d, const unsigned* a, const unsigned* b) {
    asm volatile(
        "mma.sync.aligned.m16n8k8.row.col.f32.tf32.tf32.f32 "
        "{%0,%1,%2,%3}, {%4,%5,%6,%7}, {%8,%9}, {%0,%1,%2,%3};"
        : "+f"(d[0]), "+f"(d[1]), "+f"(d[2]), "+f"(d[3])
        : "r"(a[0]), "r"(a[1]), "r"(a[2]), "r"(a[3]),
          "r"(b[0]), "r"(b[1]));
}

// ------------------------- fused 4-way GEMM (TF32 mma.sync) ------------------
// Concatenated output columns = 1664 = 13 tiles of 128.
// Tiles 0-3 -> q (fp32), 4-7 -> k (bf16), 8-11 -> v (bf16), 12 -> skip (fp32).
// BM=128, BN=128, BK=16; 8 warps in 2(m) x 4(n); warp tile 64x32.
#define SA_STRIDE 20
#define SB_STRIDE 136
__global__ __launch_bounds__(256, 2)
void gemm4_kernel(const float* __restrict__ X, int rows, int K,
                  const float* __restrict__ Wq, const float* __restrict__ bq, float* __restrict__ oq,
                  const float* __restrict__ Wk, const float* __restrict__ bk, __nv_bfloat16* __restrict__ okb,
                  const float* __restrict__ Wv, const float* __restrict__ bv, __nv_bfloat16* __restrict__ ovb,
                  const float* __restrict__ Wsk, const float* __restrict__ bsk, float* __restrict__ osk)
{
    __shared__ float sA[128][SA_STRIDE];
    __shared__ float sB[16][SB_STRIDE];

    int tid  = threadIdx.x;
    int wid  = tid >> 5;
    int lane = tid & 31;
    int warp_m = wid >> 2;          // 0..1
    int warp_n = wid & 3;           // 0..3
    int m0w = warp_m * 64;
    int n0w = warp_n * 32;

    int tile = blockIdx.x;          // 0..12
    int seg = tile >> 2;
    int c0 = (tile & 3) * 128;

    const float* W; const float* bias; int oc;
    if (seg == 0)      { W = Wq;  bias = bq;  oc = HC; }
    else if (seg == 1) { W = Wk;  bias = bk;  oc = HC; }
    else if (seg == 2) { W = Wv;  bias = bv;  oc = HC; }
    else               { W = Wsk; bias = bsk; oc = DD; }

    int row0 = blockIdx.y * 128;

    float acc[4][4][4];             // [mt][nt][reg]
    #pragma unroll
    for (int i = 0; i < 4; i++)
        #pragma unroll
        for (int j = 0; j < 4; j++)
            #pragma unroll
            for (int r = 0; r < 4; r++) acc[i][j][r] = 0.f;

    int rloc = lane >> 2;           // 0..7
    int cloc = lane & 3;            // 0..3

    for (int k0 = 0; k0 < K; k0 += 16) {
        // fill sA: 128x16 (2 float4 per thread), tf32-rounded
        #pragma unroll
        for (int t = 0; t < 2; ++t) {
            int s = tid + t * 256;      // 0..511
            int r = s >> 2;             // 0..127
            int kq = (s & 3) * 4;
            int gr = row0 + r;
            float4 xv = (gr < rows)
                ? *reinterpret_cast<const float4*>(X + (size_t)gr * K + k0 + kq)
                : make_float4(0.f, 0.f, 0.f, 0.f);
            xv.x = to_tf32(xv.x); xv.y = to_tf32(xv.y);
            xv.z = to_tf32(xv.z); xv.w = to_tf32(xv.w);
            *reinterpret_cast<float4*>(&sA[r][kq]) = xv;
        }
        // fill sB: 16x128, tf32-rounded
        #pragma unroll
        for (int t = 0; t < 2; ++t) {
            int s = tid + t * 256;
            int kr = s >> 5;            // 0..15
            int cq = (s & 31) * 4;
            float4 wv = *reinterpret_cast<const float4*>(W + (size_t)(k0 + kr) * oc + c0 + cq);
            wv.x = to_tf32(wv.x); wv.y = to_tf32(wv.y);
            wv.z = to_tf32(wv.z); wv.w = to_tf32(wv.w);
            *reinterpret_cast<float4*>(&sB[kr][cq]) = wv;
        }
        __syncthreads();

        #pragma unroll
        for (int ks = 0; ks < 2; ++ks) {
            int kb8 = ks * 8;
            unsigned afr[4][4];
            #pragma unroll
            for (int mt = 0; mt < 4; ++mt) {
                int mrow = m0w + mt * 16 + rloc;
                afr[mt][0] = __float_as_uint(sA[mrow    ][kb8 + cloc]);
                afr[mt][1] = __float_as_uint(sA[mrow + 8][kb8 + cloc]);
                afr[mt][2] = __float_as_uint(sA[mrow    ][kb8 + cloc + 4]);
                afr[mt][3] = __float_as_uint(sA[mrow + 8][kb8 + cloc + 4]);
            }
            unsigned bfr[4][2];
            #pragma unroll
            for (int nt = 0; nt < 4; ++nt) {
                int ncol = n0w + nt * 8 + rloc;
                bfr[nt][0] = __float_as_uint(sB[kb8 + cloc    ][ncol]);
                bfr[nt][1] = __float_as_uint(sB[kb8 + cloc + 4][ncol]);
            }
            #pragma unroll
            for (int mt = 0; mt < 4; ++mt)
                #pragma unroll
                for (int nt = 0; nt < 4; ++nt)
                    mma_tf32(acc[mt][nt], afr[mt], bfr[nt]);
        }
        __syncthreads();
    }

    // epilogue: c0/c1 -> (row=rloc, cols 2*cloc, 2*cloc+1); c2/c3 -> row+8
    #pragma unroll
    for (int mt = 0; mt < 4; ++mt) {
        int gr0 = row0 + m0w + mt * 16 + rloc;
        int gr1 = gr0 + 8;
        #pragma unroll
        for (int nt = 0; nt < 4; ++nt) {
            int colL = n0w + nt * 8 + cloc * 2;      // within 128-tile
            int gcol = c0 + colL;                     // within segment
            float b0 = __ldg(&bias[gcol]);
            float b1 = __ldg(&bias[gcol + 1]);
            float v00 = acc[mt][nt][0] + b0, v01 = acc[mt][nt][1] + b1;
            float v10 = acc[mt][nt][2] + b0, v11 = acc[mt][nt][3] + b1;
            if (seg == 0 || seg == 3) {
                float* Y = (seg == 0) ? oq : osk;
                if (gr0 < rows)
                    *reinterpret_cast<float2*>(Y + (size_t)gr0 * oc + gcol) = make_float2(v00, v01);
                if (gr1 < rows)
                    *reinterpret_cast<float2*>(Y + (size_t)gr1 * oc + gcol) = make_float2(v10, v11);
            } else {
                __nv_bfloat16* Y = (seg == 1) ? okb : ovb;
                if (gr0 < rows)
                    *reinterpret_cast<unsigned*>(Y + (size_t)gr0 * oc + gcol) = pack_bf2(v00, v01);
                if (gr1 < rows)
                    *reinterpret_cast<unsigned*>(Y + (size_t)gr1 * oc + gcol) = pack_bf2(v10, v11);
            }
        }
    }
}

// ------------------------- fused attention per node -------------------------
__device__ __forceinline__ float4 bf4_to_f4(uint2 raw) {
    __nv_bfloat162 p0 = *reinterpret_cast<__nv_bfloat162*>(&raw.x);
    __nv_bfloat162 p1 = *reinterpret_cast<__nv_bfloat162*>(&raw.y);
    float2 f0 = __bfloat1622float2(p0);
    float2 f1 = __bfloat1622float2(p1);
    return make_float4(f0.x, f0.y, f1.x, f1.y);
}

__global__ void attn_kernel(const float* __restrict__ q,
                            const __nv_bfloat16* __restrict__ kb,
                            const __nv_bfloat16* __restrict__ vb,
                            const float* __restrict__ s,
                            const int* __restrict__ row, const int* __restrict__ srcs,
                            float* __restrict__ out) {
    int n = blockIdx.x;
    int tid = threadIdx.x;
    int h = tid >> 5;
    int lane = tid & 31;
    __shared__ float sh[HH][CC];

    const float4 qv = reinterpret_cast<const float4*>(q + (size_t)n * HC + h * CC)[lane];
    int beg = row[n], end = row[n + 1];
    size_t hoff = (size_t)h * CC;

    float m = -INFINITY, l = 0.f;
    float4 acc = make_float4(0.f, 0.f, 0.f, 0.f);

    int deg = end - beg;
    int ng = deg >> 2;

    uint2 kc[4], vc[4], kn[4], vn[4];

    if (ng > 0) {
        #pragma unroll
        for (int e = 0; e < 4; ++e) {
            int si = __ldg(&srcs[beg + e]);
            kc[e] = reinterpret_cast<const uint2*>(kb + (size_t)si * HC + hoff)[lane];
            vc[e] = reinterpret_cast<const uint2*>(vb + (size_t)si * HC + hoff)[lane];
        }
    }

    for (int g = 0; g < ng; ++g) {
        if (g + 1 < ng) {
            int b2 = beg + (g + 1) * 4;
            #pragma unroll
            for (int e = 0; e < 4; ++e) {
                int si = __ldg(&srcs[b2 + e]);
                kn[e] = reinterpret_cast<const uint2*>(kb + (size_t)si * HC + hoff)[lane];
                vn[e] = reinterpret_cast<const uint2*>(vb + (size_t)si * HC + hoff)[lane];
            }
        }
        float d[4];
        #pragma unroll
        for (int e = 0; e < 4; ++e) {
            float4 kv = bf4_to_f4(kc[e]);
            d[e] = qv.x * kv.x + qv.y * kv.y + qv.z * kv.z + qv.w * kv.w;
        }
        #pragma unroll
        for (int off = 16; off > 0; off >>= 1) {
            #pragma unroll
            for (int e = 0; e < 4; ++e)
                d[e] += __shfl_xor_sync(0xffffffffu, d[e], off);
        }
        float a0 = d[0] * SCALE, a1 = d[1] * SCALE;
        float a2 = d[2] * SCALE, a3 = d[3] * SCALE;
        float m2 = fmaxf(fmaxf(fmaxf(a0, a1), fmaxf(a2, a3)), m);
        float cf = __expf(m - m2);
        float p0 = __expf(a0 - m2), p1 = __expf(a1 - m2);
        float p2 = __expf(a2 - m2), p3 = __expf(a3 - m2);
        float4 f0 = bf4_to_f4(vc[0]), f1 = bf4_to_f4(vc[1]);
        float4 f2 = bf4_to_f4(vc[2]), f3 = bf4_to_f4(vc[3]);
        acc.x = acc.x * cf + (p0 * f0.x + p1 * f1.x) + (p2 * f2.x + p3 * f3.x);
        acc.y = acc.y * cf + (p0 * f0.y + p1 * f1.y) + (p2 * f2.y + p3 * f3.y);
        acc.z = acc.z * cf + (p0 * f0.z + p1 * f1.z) + (p2 * f2.z + p3 * f3.z);
        acc.w = acc.w * cf + (p0 * f0.w + p1 * f1.w) + (p2 * f2.w + p3 * f3.w);
        l = l * cf + ((p0 + p1) + (p2 + p3));
        m = m2;
        #pragma unroll
        for (int e = 0; e < 4; ++e) { kc[e] = kn[e]; vc[e] = vn[e]; }
    }

    for (int j = beg + ng * 4; j < end; ++j) {
        int si = __ldg(&srcs[j]);
        uint2 kr = reinterpret_cast<const uint2*>(kb + (size_t)si * HC + hoff)[lane];
        uint2 vr = reinterpret_cast<const uint2*>(vb + (size_t)si * HC + hoff)[lane];
        float4 kv = bf4_to_f4(kr);
        float part = qv.x * kv.x + qv.y * kv.y + qv.z * kv.z + qv.w * kv.w;
        #pragma unroll
        for (int off = 16; off > 0; off >>= 1)
            part += __shfl_xor_sync(0xffffffffu, part, off);
        float alpha = part * SCALE;
        float m2 = fmaxf(m, alpha);
        float cf = __expf(m - m2);
        float p  = __expf(alpha - m2);
        float4 vv = bf4_to_f4(vr);
        acc.x = acc.x * cf + p * vv.x;
        acc.y = acc.y * cf + p * vv.y;
        acc.z = acc.z * cf + p * vv.z;
        acc.w = acc.w * cf + p * vv.w;
        l = l * cf + p;
        m = m2;
    }

    float invl = 1.f / (l + 1e-16f);
    sh[h][lane * 4 + 0] = acc.x * invl;
    sh[h][lane * 4 + 1] = acc.y * invl;
    sh[h][lane * 4 + 2] = acc.z * invl;
    sh[h][lane * 4 + 3] = acc.w * invl;
    __syncthreads();

    float val = (sh[0][tid] + sh[1][tid] + sh[2][tid] + sh[3][tid]) * 0.25f
              + s[(size_t)n * DD + tid];
    out[(size_t)n * DD + tid] = fmaxf(val, 0.f);
}

// ------------------------- tail: mean over nodes, fc, sigmoid ---------------
__global__ void reduce_cols_kernel(const float* __restrict__ hbuf, float* __restrict__ g) {
    int c = threadIdx.x;
    float a = 0.f;
    for (int r = blockIdx.x; r < NN; r += gridDim.x)
        a += hbuf[(size_t)r * DD + c];
    atomicAdd(&g[c], a);
}

__global__ void fc_kernel(const float* __restrict__ g, const float* __restrict__ Wfc,
                          const float* __restrict__ bfc, float* __restrict__ out) {
    int tid = threadIdx.x;
    float x = g[tid] * (1.0f / (float)NN) * Wfc[tid];
    #pragma unroll
    for (int off = 16; off > 0; off >>= 1)
        x += __shfl_xor_sync(0xffffffffu, x, off);
    __shared__ float ws[4];
    if ((tid & 31) == 0) ws[tid >> 5] = x;
    __syncthreads();
    if (tid == 0) {
        float sum = ws[0] + ws[1] + ws[2] + ws[3] + bfc[0];
        out[0] = 1.f / (1.f + expf(-sum));
    }
}

// ------------------------- launch -------------------------------------------
extern "C" void kernel_launch(void* const* d_in, const int* in_sizes, int n_in,
                              void* d_out, int out_size) {
    (void)in_sizes; (void)n_in; (void)out_size;

    const float* x    = (const float*)d_in[0];
    const int*   eidx = (const int*)d_in[1];
    const int*   src  = eidx;
    const int*   dst  = eidx + EE;
    const float* Wfc  = (const float*)d_in[26];
    const float* bfc  = (const float*)d_in[27];
    float* out = (float*)d_out;

    int *row, *cnt, *cursor, *srcs;
    float *q, *s, *hA, *hB, *g;
    __nv_bfloat16 *kbp, *vbp;
    cudaGetSymbolAddress((void**)&row,    g_row);
    cudaGetSymbolAddress((void**)&cnt,    g_cnt);
    cudaGetSymbolAddress((void**)&cursor, g_cursor);
    cudaGetSymbolAddress((void**)&srcs,   g_srcs);
    cudaGetSymbolAddress((void**)&q,      g_q);
    cudaGetSymbolAddress((void**)&kbp,    g_kb);
    cudaGetSymbolAddress((void**)&vbp,    g_vb);
    cudaGetSymbolAddress((void**)&s,      g_s);
    cudaGetSymbolAddress((void**)&hA,     g_hA);
    cudaGetSymbolAddress((void**)&hB,     g_hB);
    cudaGetSymbolAddress((void**)&g,      g_g);

    // ---- CSR build ----
    zero_kernel<<<(NN + 256) / 256, 256>>>(cnt, g);
    hist_kernel<<<(EE + 255) / 256, 256>>>(dst, cnt);
    scan_kernel<<<1, 1024>>>(cnt, row, cursor);
    fill_kernel<<<(EE + 255) / 256, 256>>>(src, dst, cursor, srcs);

    // ---- 3 transformer-conv layers ----
    const float* X = x;
    int fin = 64;
    float* hout = hA;
    for (int l = 0; l < 3; ++l) {
        const float* Wq = (const float*)d_in[2 + 8 * l + 0];
        const float* bq = (const float*)d_in[2 + 8 * l + 1];
        const float* Wk = (const float*)d_in[2 + 8 * l + 2];
        const float* bk = (const float*)d_in[2 + 8 * l + 3];
        const float* Wv = (const float*)d_in[2 + 8 * l + 4];
        const float* bv = (const float*)d_in[2 + 8 * l + 5];
        const float* Ws = (const float*)d_in[2 + 8 * l + 6];
        const float* bs = (const float*)d_in[2 + 8 * l + 7];

        dim3 grid(13, (NN + 127) / 128);
        gemm4_kernel<<<grid, 256>>>(X, NN, fin,
                                    Wq, bq, q,
                                    Wk, bk, kbp,
                                    Wv, bv, vbp,
                                    Ws, bs, s);

        attn_kernel<<<NN, 128>>>(q, kbp, vbp, s, row, srcs, hout);

        X = hout;
        hout = (hout == hA) ? hB : hA;
        fin = DD;
    }

    // ---- global mean + fc + sigmoid ----
    reduce_cols_kernel<<<256, 128>>>(X, g);
    fc_kernel<<<1, 128>>>(g, Wfc, bfc, out);
}

// round 7
// speedup vs baseline: 2.6847x; 1.0189x over previous
#include <cuda_runtime.h>
#include <cuda_bf16.h>
#include <math.h>

// Problem constants (fixed by the dataset)
#define NN 25000
#define EE 400000
#define HH 4
#define CC 128
#define DD 128
#define HC 512           // H*C
#define SCALE 0.08838834764831845f   // 1/sqrt(128)

// ------------------------- device scratch (no runtime allocs) ---------------
static __device__ int   g_row[NN + 1];
static __device__ int   g_cnt[NN + 1];
static __device__ int   g_cursor[NN + 1];
static __device__ int   g_srcs[EE];
static __device__ float g_q[NN * HC];
static __device__ __nv_bfloat16 g_kb[NN * HC];
static __device__ __nv_bfloat16 g_vb[NN * HC];
static __device__ float g_s[NN * DD];
static __device__ float g_hA[NN * DD];
static __device__ float g_hB[NN * DD];
static __device__ float g_g[DD];

// ------------------------- zero scratch -------------------------------------
__global__ void zero_kernel(int* __restrict__ cnt, float* __restrict__ g) {
    int i = blockIdx.x * blockDim.x + threadIdx.x;
    if (i < NN + 1) cnt[i] = 0;
    if (i < DD) g[i] = 0.f;
}

// ------------------------- CSR build ----------------------------------------
__global__ void hist_kernel(const int* __restrict__ dst, int* __restrict__ cnt) {
    int e = blockIdx.x * blockDim.x + threadIdx.x;
    if (e < EE) atomicAdd(&cnt[dst[e]], 1);
}

__global__ void scan_kernel(const int* __restrict__ cnt,
                            int* __restrict__ row, int* __restrict__ cursor) {
    __shared__ int buf[1024];
    __shared__ int carry;
    int tid = threadIdx.x;
    if (tid == 0) carry = 0;
    __syncthreads();
    for (int base = 0; base < NN; base += 1024) {
        int i = base + tid;
        int v = (i < NN) ? cnt[i] : 0;
        buf[tid] = v;
        __syncthreads();
        #pragma unroll
        for (int off = 1; off < 1024; off <<= 1) {
            int t = (tid >= off) ? buf[tid - off] : 0;
            __syncthreads();
            buf[tid] += t;
            __syncthreads();
        }
        int incl = buf[tid];
        int excl = incl - v + carry;
        if (i < NN) { row[i] = excl; cursor[i] = excl; }
        __syncthreads();
        if (tid == 1023) carry += buf[1023];
        __syncthreads();
    }
    if (tid == 0) row[NN] = carry;
}

__global__ void fill_kernel(const int* __restrict__ src, const int* __restrict__ dst,
                            int* __restrict__ cursor, int* __restrict__ srcs) {
    int e = blockIdx.x * blockDim.x + threadIdx.x;
    if (e < EE) {
        int p = atomicAdd(&cursor[dst[e]], 1);
        srcs[p] = src[e];
    }
}

// ------------------------- helpers ------------------------------------------
__device__ __forceinline__ unsigned pack_bf2(float lo, float hi) {
    unsigned r;
    asm("cvt.rn.bf16x2.f32 %0, %1, %2;" : "=r"(r) : "f"(hi), "f"(lo));
    return r;
}
__device__ __forceinline__ void ldsm_x4(unsigned* r, const void* p) {
    unsigned addr = (unsigned)__cvta_generic_to_shared(p);
    asm volatile("ldmatrix.sync.aligned.m8n8.x4.shared.b16 {%0,%1,%2,%3}, [%4];"
                 : "=r"(r[0]), "=r"(r[1]), "=r"(r[2]), "=r"(r[3]) : "r"(addr));
}
__device__ __forceinline__ void ldsm_x2t(unsigned* r, const void* p) {
    unsigned addr = (unsigned)__cvta_generic_to_shared(p);
    asm volatile("ldmatrix.sync.aligned.m8n8.x2.trans.shared.b16 {%0,%1}, [%2];"
                 : "=r"(r[0]), "=r"(r[1]) : "r"(addr));
}
__device__ __forceinline__ void mma_bf16(float* d, const unsigned* a, const unsigned* b) {
    asm volatile(
        "mma.sync.aligned.m16n8k16.row.col.f32.bf16.bf16.f32 "
        "{%0,%1,%2,%3}, {%4,%5,%6,%7}, {%8,%9}, {%0,%1,%2,%3};"
        : "+f"(d[0]), "+f"(d[1]), "+f"(d[2]), "+f"(d[3])
        : "r"(a[0]), "r"(a[1]), "r"(a[2]), "r"(a[3]),
          "r"(b[0]), "r"(b[1]));
}

// ------------------------- fused 4-way GEMM (bf16 mma + ldmatrix) ------------
// Concatenated output columns = 1664 = 13 tiles of 128.
// Tiles 0-3 -> q (fp32), 4-7 -> k (bf16), 8-11 -> v (bf16), 12 -> skip (fp32).
// BM=128, BN=128, BK=32; 8 warps in 2(m) x 4(n); warp tile 64x32.
#define SA_STRIDE 40     // bf16 units (80B rows) — ldmatrix conflict-free
#define SB_STRIDE 136    // bf16 units (272B rows) — ldmatrix conflict-free
__global__ __launch_bounds__(256, 2)
void gemm4_kernel(const float* __restrict__ X, int rows, int K,
                  const float* __restrict__ Wq, const float* __restrict__ bq, float* __restrict__ oq,
                  const float* __restrict__ Wk, const float* __restrict__ bk, __nv_bfloat16* __restrict__ okb,
                  const float* __restrict__ Wv, const float* __restrict__ bv, __nv_bfloat16* __restrict__ ovb,
                  const float* __restrict__ Wsk, const float* __restrict__ bsk, float* __restrict__ osk)
{
    __shared__ __nv_bfloat16 sA[128][SA_STRIDE];
    __shared__ __nv_bfloat16 sB[32][SB_STRIDE];

    int tid  = threadIdx.x;
    int wid  = tid >> 5;
    int lane = tid & 31;
    int warp_m = wid >> 2;          // 0..1
    int warp_n = wid & 3;           // 0..3
    int m0w = warp_m * 64;
    int n0w = warp_n * 32;

    int tile = blockIdx.x;          // 0..12
    int seg = tile >> 2;
    int c0 = (tile & 3) * 128;

    const float* W; const float* bias; int oc;
    if (seg == 0)      { W = Wq;  bias = bq;  oc = HC; }
    else if (seg == 1) { W = Wk;  bias = bk;  oc = HC; }
    else if (seg == 2) { W = Wv;  bias = bv;  oc = HC; }
    else               { W = Wsk; bias = bsk; oc = DD; }

    int row0 = blockIdx.y * 128;

    float acc[4][4][4];             // [mt][nt][reg]
    #pragma unroll
    for (int i = 0; i < 4; i++)
        #pragma unroll
        for (int j = 0; j < 4; j++)
            #pragma unroll
            for (int r = 0; r < 4; r++) acc[i][j][r] = 0.f;

    int rloc = lane >> 2;           // 0..7
    int cloc = lane & 3;            // 0..3

    // fill thread mappings
    int fa_r    = tid >> 1;          // 0..127
    int fa_c0   = (tid & 1) * 16;    // 0 or 16
    int fb_k    = tid >> 3;          // 0..31
    int fb_n0   = (tid & 7) * 16;    // 0..112

    for (int k0 = 0; k0 < K; k0 += 32) {
        // ---- fill sA: 128x32 fp32 -> bf16 ----
        {
            int gr = row0 + fa_r;
            const float* xp = X + (size_t)gr * K + k0 + fa_c0;
            #pragma unroll
            for (int i = 0; i < 4; ++i) {
                float4 xv = (gr < rows)
                    ? *reinterpret_cast<const float4*>(xp + i * 4)
                    : make_float4(0.f, 0.f, 0.f, 0.f);
                uint2 pk;
                pk.x = pack_bf2(xv.x, xv.y);
                pk.y = pack_bf2(xv.z, xv.w);
                *reinterpret_cast<uint2*>(&sA[fa_r][fa_c0 + i * 4]) = pk;
            }
        }
        // ---- fill sB: 32x128 fp32 -> bf16 ----
        {
            const float* wp = W + (size_t)(k0 + fb_k) * oc + c0 + fb_n0;
            #pragma unroll
            for (int i = 0; i < 4; ++i) {
                float4 wv = *reinterpret_cast<const float4*>(wp + i * 4);
                uint2 pk;
                pk.x = pack_bf2(wv.x, wv.y);
                pk.y = pack_bf2(wv.z, wv.w);
                *reinterpret_cast<uint2*>(&sB[fb_k][fb_n0 + i * 4]) = pk;
            }
        }
        __syncthreads();

        #pragma unroll
        for (int ks = 0; ks < 32; ks += 16) {
            unsigned afr[4][4];
            #pragma unroll
            for (int mt = 0; mt < 4; ++mt)
                ldsm_x4(afr[mt], &sA[m0w + mt * 16 + (lane & 15)][ks + (lane >> 4) * 8]);
            unsigned bfr[4][2];
            #pragma unroll
            for (int nt = 0; nt < 4; ++nt)
                ldsm_x2t(bfr[nt], &sB[ks + (lane & 15)][n0w + nt * 8]);
            #pragma unroll
            for (int mt = 0; mt < 4; ++mt)
                #pragma unroll
                for (int nt = 0; nt < 4; ++nt)
                    mma_bf16(acc[mt][nt], afr[mt], bfr[nt]);
        }
        __syncthreads();
    }

    // epilogue: c0/c1 -> (row=rloc, cols 2*cloc, +1); c2/c3 -> row+8
    #pragma unroll
    for (int mt = 0; mt < 4; ++mt) {
        int gr0 = row0 + m0w + mt * 16 + rloc;
        int gr1 = gr0 + 8;
        #pragma unroll
        for (int nt = 0; nt < 4; ++nt) {
            int gcol = c0 + n0w + nt * 8 + cloc * 2;
            float b0 = __ldg(&bias[gcol]);
            float b1 = __ldg(&bias[gcol + 1]);
            float v00 = acc[mt][nt][0] + b0, v01 = acc[mt][nt][1] + b1;
            float v10 = acc[mt][nt][2] + b0, v11 = acc[mt][nt][3] + b1;
            if (seg == 0 || seg == 3) {
                float* Y = (seg == 0) ? oq : osk;
                if (gr0 < rows)
                    *reinterpret_cast<float2*>(Y + (size_t)gr0 * oc + gcol) = make_float2(v00, v01);
                if (gr1 < rows)
                    *reinterpret_cast<float2*>(Y + (size_t)gr1 * oc + gcol) = make_float2(v10, v11);
            } else {
                __nv_bfloat16* Y = (seg == 1) ? okb : ovb;
                if (gr0 < rows)
                    *reinterpret_cast<unsigned*>(Y + (size_t)gr0 * oc + gcol) = pack_bf2(v00, v01);
                if (gr1 < rows)
                    *reinterpret_cast<unsigned*>(Y + (size_t)gr1 * oc + gcol) = pack_bf2(v10, v11);
            }
        }
    }
}

// ------------------------- fused attention per node -------------------------
__device__ __forceinline__ float4 bf4_to_f4(uint2 raw) {
    __nv_bfloat162 p0 = *reinterpret_cast<__nv_bfloat162*>(&raw.x);
    __nv_bfloat162 p1 = *reinterpret_cast<__nv_bfloat162*>(&raw.y);
    float2 f0 = __bfloat1622float2(p0);
    float2 f1 = __bfloat1622float2(p1);
    return make_float4(f0.x, f0.y, f1.x, f1.y);
}

__global__ void attn_kernel(const float* __restrict__ q,
                            const __nv_bfloat16* __restrict__ kb,
                            const __nv_bfloat16* __restrict__ vb,
                            const float* __restrict__ s,
                            const int* __restrict__ row, const int* __restrict__ srcs,
                            float* __restrict__ out) {
    int n = blockIdx.x;
    int tid = threadIdx.x;
    int h = tid >> 5;
    int lane = tid & 31;
    __shared__ float sh[HH][CC];

    const float4 qv = reinterpret_cast<const float4*>(q + (size_t)n * HC + h * CC)[lane];
    int beg = row[n], end = row[n + 1];
    size_t hoff = (size_t)h * CC;

    float m = -INFINITY, l = 0.f;
    float4 acc = make_float4(0.f, 0.f, 0.f, 0.f);

    int deg = end - beg;
    int ng = deg >> 2;

    uint2 kc[4], vc[4], kn[4], vn[4];

    if (ng > 0) {
        #pragma unroll
        for (int e = 0; e < 4; ++e) {
            int si = __ldg(&srcs[beg + e]);
            kc[e] = reinterpret_cast<const uint2*>(kb + (size_t)si * HC + hoff)[lane];
            vc[e] = reinterpret_cast<const uint2*>(vb + (size_t)si * HC + hoff)[lane];
        }
    }

    for (int g = 0; g < ng; ++g) {
        if (g + 1 < ng) {
            int b2 = beg + (g + 1) * 4;
            #pragma unroll
            for (int e = 0; e < 4; ++e) {
                int si = __ldg(&srcs[b2 + e]);
                kn[e] = reinterpret_cast<const uint2*>(kb + (size_t)si * HC + hoff)[lane];
                vn[e] = reinterpret_cast<const uint2*>(vb + (size_t)si * HC + hoff)[lane];
            }
        }
        float d[4];
        #pragma unroll
        for (int e = 0; e < 4; ++e) {
            float4 kv = bf4_to_f4(kc[e]);
            d[e] = qv.x * kv.x + qv.y * kv.y + qv.z * kv.z + qv.w * kv.w;
        }
        #pragma unroll
        for (int off = 16; off > 0; off >>= 1) {
            #pragma unroll
            for (int e = 0; e < 4; ++e)
                d[e] += __shfl_xor_sync(0xffffffffu, d[e], off);
        }
        float a0 = d[0] * SCALE, a1 = d[1] * SCALE;
        float a2 = d[2] * SCALE, a3 = d[3] * SCALE;
        float m2 = fmaxf(fmaxf(fmaxf(a0, a1), fmaxf(a2, a3)), m);
        float cf = __expf(m - m2);
        float p0 = __expf(a0 - m2), p1 = __expf(a1 - m2);
        float p2 = __expf(a2 - m2), p3 = __expf(a3 - m2);
        float4 f0 = bf4_to_f4(vc[0]), f1 = bf4_to_f4(vc[1]);
        float4 f2 = bf4_to_f4(vc[2]), f3 = bf4_to_f4(vc[3]);
        acc.x = acc.x * cf + (p0 * f0.x + p1 * f1.x) + (p2 * f2.x + p3 * f3.x);
        acc.y = acc.y * cf + (p0 * f0.y + p1 * f1.y) + (p2 * f2.y + p3 * f3.y);
        acc.z = acc.z * cf + (p0 * f0.z + p1 * f1.z) + (p2 * f2.z + p3 * f3.z);
        acc.w = acc.w * cf + (p0 * f0.w + p1 * f1.w) + (p2 * f2.w + p3 * f3.w);
        l = l * cf + ((p0 + p1) + (p2 + p3));
        m = m2;
        #pragma unroll
        for (int e = 0; e < 4; ++e) { kc[e] = kn[e]; vc[e] = vn[e]; }
    }

    for (int j = beg + ng * 4; j < end; ++j) {
        int si = __ldg(&srcs[j]);
        uint2 kr = reinterpret_cast<const uint2*>(kb + (size_t)si * HC + hoff)[lane];
        uint2 vr = reinterpret_cast<const uint2*>(vb + (size_t)si * HC + hoff)[lane];
        float4 kv = bf4_to_f4(kr);
        float part = qv.x * kv.x + qv.y * kv.y + qv.z * kv.z + qv.w * kv.w;
        #pragma unroll
        for (int off = 16; off > 0; off >>= 1)
            part += __shfl_xor_sync(0xffffffffu, part, off);
        float alpha = part * SCALE;
        float m2 = fmaxf(m, alpha);
        float cf = __expf(m - m2);
        float p  = __expf(alpha - m2);
        float4 vv = bf4_to_f4(vr);
        acc.x = acc.x * cf + p * vv.x;
        acc.y = acc.y * cf + p * vv.y;
        acc.z = acc.z * cf + p * vv.z;
        acc.w = acc.w * cf + p * vv.w;
        l = l * cf + p;
        m = m2;
    }

    float invl = 1.f / (l + 1e-16f);
    sh[h][lane * 4 + 0] = acc.x * invl;
    sh[h][lane * 4 + 1] = acc.y * invl;
    sh[h][lane * 4 + 2] = acc.z * invl;
    sh[h][lane * 4 + 3] = acc.w * invl;
    __syncthreads();

    float val = (sh[0][tid] + sh[1][tid] + sh[2][tid] + sh[3][tid]) * 0.25f
              + s[(size_t)n * DD + tid];
    out[(size_t)n * DD + tid] = fmaxf(val, 0.f);
}

// ------------------------- tail: mean over nodes, fc, sigmoid ---------------
__global__ void reduce_cols_kernel(const float* __restrict__ hbuf, float* __restrict__ g) {
    int c = threadIdx.x;
    float a = 0.f;
    for (int r = blockIdx.x; r < NN; r += gridDim.x)
        a += hbuf[(size_t)r * DD + c];
    atomicAdd(&g[c], a);
}

__global__ void fc_kernel(const float* __restrict__ g, const float* __restrict__ Wfc,
                          const float* __restrict__ bfc, float* __restrict__ out) {
    int tid = threadIdx.x;
    float x = g[tid] * (1.0f / (float)NN) * Wfc[tid];
    #pragma unroll
    for (int off = 16; off > 0; off >>= 1)
        x += __shfl_xor_sync(0xffffffffu, x, off);
    __shared__ float ws[4];
    if ((tid & 31) == 0) ws[tid >> 5] = x;
    __syncthreads();
    if (tid == 0) {
        float sum = ws[0] + ws[1] + ws[2] + ws[3] + bfc[0];
        out[0] = 1.f / (1.f + expf(-sum));
    }
}

// ------------------------- launch -------------------------------------------
extern "C" void kernel_launch(void* const* d_in, const int* in_sizes, int n_in,
                              void* d_out, int out_size) {
    (void)in_sizes; (void)n_in; (void)out_size;

    const float* x    = (const float*)d_in[0];
    const int*   eidx = (const int*)d_in[1];
    const int*   src  = eidx;
    const int*   dst  = eidx + EE;
    const float* Wfc  = (const float*)d_in[26];
    const float* bfc  = (const float*)d_in[27];
    float* out = (float*)d_out;

    int *row, *cnt, *cursor, *srcs;
    float *q, *s, *hA, *hB, *g;
    __nv_bfloat16 *kbp, *vbp;
    cudaGetSymbolAddress((void**)&row,    g_row);
    cudaGetSymbolAddress((void**)&cnt,    g_cnt);
    cudaGetSymbolAddress((void**)&cursor, g_cursor);
    cudaGetSymbolAddress((void**)&srcs,   g_srcs);
    cudaGetSymbolAddress((void**)&q,      g_q);
    cudaGetSymbolAddress((void**)&kbp,    g_kb);
    cudaGetSymbolAddress((void**)&vbp,    g_vb);
    cudaGetSymbolAddress((void**)&s,      g_s);
    cudaGetSymbolAddress((void**)&hA,     g_hA);
    cudaGetSymbolAddress((void**)&hB,     g_hB);
    cudaGetSymbolAddress((void**)&g,      g_g);

    // ---- CSR build ----
    zero_kernel<<<(NN + 256) / 256, 256>>>(cnt, g);
    hist_kernel<<<(EE + 255) / 256, 256>>>(dst, cnt);
    scan_kernel<<<1, 1024>>>(cnt, row, cursor);
    fill_kernel<<<(EE + 255) / 256, 256>>>(src, dst, cursor, srcs);

    // ---- 3 transformer-conv layers ----
    const float* X = x;
    int fin = 64;
    float* hout = hA;
    for (int l = 0; l < 3; ++l) {
        const float* Wq = (const float*)d_in[2 + 8 * l + 0];
        const float* bq = (const float*)d_in[2 + 8 * l + 1];
        const float* Wk = (const float*)d_in[2 + 8 * l + 2];
        const float* bk = (const float*)d_in[2 + 8 * l + 3];
        const float* Wv = (const float*)d_in[2 + 8 * l + 4];
        const float* bv = (const float*)d_in[2 + 8 * l + 5];
        const float* Ws = (const float*)d_in[2 + 8 * l + 6];
        const float* bs = (const float*)d_in[2 + 8 * l + 7];

        dim3 grid(13, (NN + 127) / 128);
        gemm4_kernel<<<grid, 256>>>(X, NN, fin,
                                    Wq, bq, q,
                                    Wk, bk, kbp,
                                    Wv, bv, vbp,
                                    Ws, bs, s);

        attn_kernel<<<NN, 128>>>(q, kbp, vbp, s, row, srcs, hout);

        X = hout;
        hout = (hout == hA) ? hB : hA;
        fin = DD;
    }

    // ---- global mean + fc + sigmoid ----
    reduce_cols_kernel<<<256, 128>>>(X, g);
    fc_kernel<<<1, 128>>>(g, Wfc, bfc, out);
}